// round 12
// baseline (speedup 1.0000x reference)
#include <cuda_runtime.h>
#include <math.h>
#include <stdint.h>

// Problem constants
#define BB   2
#define SS   2048
#define DDIM 1024
#define HH   16
#define DK   64
#define FFD  4096
#define MTOT (BB*SS)   // 4096 rows

// ---------------------------------------------------------------------------
// Scratch buffers (device globals; no runtime allocation allowed)
// ---------------------------------------------------------------------------
__device__ float g_xn [MTOT*DDIM];
__device__ float g_q  [MTOT*DDIM];
__device__ float g_k  [MTOT*DDIM];
__device__ float g_v  [MTOT*DDIM];
__device__ float g_ctx[MTOT*DDIM];
__device__ float g_h  [MTOT*DDIM];
__device__ float g_hn [MTOT*DDIM];
__device__ float g_ff [MTOT*FFD];

// ---------------------------------------------------------------------------
// LayerNorm (faithful: unbiased std, denom = sqrt(std + eps))
// ---------------------------------------------------------------------------
__global__ __launch_bounds__(256) void ln_kernel(
    const float* __restrict__ x, const float* __restrict__ alpha,
    const float* __restrict__ beta, float* __restrict__ y)
{
    const int row = blockIdx.x;
    const float4* xr = reinterpret_cast<const float4*>(x + (size_t)row * DDIM);
    float4 vv = xr[threadIdx.x];
    float s  = vv.x + vv.y + vv.z + vv.w;
    float s2 = vv.x*vv.x + vv.y*vv.y + vv.z*vv.z + vv.w*vv.w;

    __shared__ float red0[8], red1[8];
    #pragma unroll
    for (int o = 16; o; o >>= 1) {
        s  += __shfl_xor_sync(0xffffffffu, s,  o);
        s2 += __shfl_xor_sync(0xffffffffu, s2, o);
    }
    const int warp = threadIdx.x >> 5, lane = threadIdx.x & 31;
    if (lane == 0) { red0[warp] = s; red1[warp] = s2; }
    __syncthreads();
    if (threadIdx.x == 0) {
        float t = 0.f, t2 = 0.f;
        #pragma unroll
        for (int i = 0; i < 8; i++) { t += red0[i]; t2 += red1[i]; }
        red0[0] = t; red1[0] = t2;
    }
    __syncthreads();
    s = red0[0]; s2 = red1[0];

    const float mean = s * (1.0f / DDIM);
    const float var  = fmaxf(0.f, (s2 - s * mean) * (1.0f / (DDIM - 1)));  // unbiased
    const float stdv = sqrtf(var);
    const float inv  = 1.0f / sqrtf(stdv + 1e-6f);   // sqrt(std + eps) !
    const float a0 = alpha[0], b0 = beta[0];

    float4 o;
    o.x = a0 * (vv.x - mean) * inv + b0;
    o.y = a0 * (vv.y - mean) * inv + b0;
    o.z = a0 * (vv.z - mean) * inv + b0;
    o.w = a0 * (vv.w - mean) * inv + b0;
    reinterpret_cast<float4*>(y + (size_t)row * DDIM)[threadIdx.x] = o;
}

// ---------------------------------------------------------------------------
// tf32 helpers
// ---------------------------------------------------------------------------
__device__ __forceinline__ uint32_t f2tf32(float x) {
    uint32_t r;
    asm("cvt.rna.tf32.f32 %0, %1;" : "=r"(r) : "f"(x));
    return r;
}

__device__ __forceinline__ void mma_tf32(
    float c[4], const uint32_t a[4], const uint32_t b[2])
{
    asm volatile(
        "mma.sync.aligned.m16n8k8.row.col.f32.tf32.tf32.f32 "
        "{%0,%1,%2,%3}, {%4,%5,%6,%7}, {%8,%9}, {%0,%1,%2,%3};\n"
        : "+f"(c[0]), "+f"(c[1]), "+f"(c[2]), "+f"(c[3])
        : "r"(a[0]), "r"(a[1]), "r"(a[2]), "r"(a[3]), "r"(b[0]), "r"(b[1]));
}

// ---------------------------------------------------------------------------
// Tensor-core GEMM (NT): C[M,N] = A[M,K]*W[N,K]^T + bias (+relu) (+res)
// CTA tile 128x256, K-tile 32. 8 warps as 2(m)x4(n); warp tile 64x64 via
// 4(mf)x8(nf) grid of m16n8k8 tf32 mma -> 128 B smem per MMA (vs 192 in R7).
// Fragment-major packed smem (validated layouts):
//   A: blk(mf*4+kc) stride 132 u32, within blk lane*4 (one LDS.128/frag)
//   B: blk(nf*4+kc) stride  66 u32, within blk lane*2 (one LDS.64/frag)
// M mult of 128, N mult of 256, K mult of 32.
// Dynamic smem: (32*132 + 128*66)*4 = 50688 B.
// ---------------------------------------------------------------------------
#define GEMM_AS_U32 (32*132)            // 4224
#define GEMM_BS_U32 (128*66)            // 8448
#define GEMM_SMEM_BYTES ((GEMM_AS_U32 + GEMM_BS_U32) * 4)

__global__ __launch_bounds__(256, 1) void gemm_tc(
    const float* __restrict__ A, const float* __restrict__ W,
    const float* __restrict__ bias, const float* __restrict__ res,
    float* __restrict__ C, int M, int N, int K, int relu)
{
    extern __shared__ uint32_t sm[];
    uint32_t* As = sm;
    uint32_t* Bs = sm + GEMM_AS_U32;

    const int tid  = threadIdx.x;
    const int lane = tid & 31;
    const int warp = tid >> 5;
    const int wm = warp >> 2;          // 0..1
    const int wn = warp & 3;           // 0..3
    const int g  = lane >> 2;          // 0..7
    const int t  = lane & 3;           // 0..3
    const int m0 = blockIdx.y * 128, n0 = blockIdx.x * 256;

    float acc[4][8][4];
    #pragma unroll
    for (int i = 0; i < 4; i++)
        #pragma unroll
        for (int j = 0; j < 8; j++)
            #pragma unroll
            for (int p = 0; p < 4; p++) acc[i][j][p] = 0.f;

    for (int k0 = 0; k0 < K; k0 += 32) {
        // ---- fill A (128x32) : 1024 float4 slots ----
        #pragma unroll
        for (int u = 0; u < 4; u++) {
            const int f  = tid + u * 256;
            const int r  = f >> 3;              // 0..127
            const int kq = (f & 7) << 2;        // 0..28 step 4
            const int kc = kq >> 3, lo = (kq >> 2) & 1;
            float4 a4 = *reinterpret_cast<const float4*>(
                A + (size_t)(m0 + r) * K + k0 + kq);
            const int mf = r >> 4, gg = r & 7, hi = (r >> 3) & 1;
            uint32_t* d = As + (mf*4 + kc) * 132 + gg*16 + (hi + 2*lo);
            d[0]  = f2tf32(a4.x);
            d[4]  = f2tf32(a4.y);
            d[8]  = f2tf32(a4.z);
            d[12] = f2tf32(a4.w);
        }
        // ---- fill B (256x32) : 2048 float4 slots ----
        #pragma unroll
        for (int u = 0; u < 8; u++) {
            const int f  = tid + u * 256;
            const int r  = f >> 3;              // 0..255
            const int kq = (f & 7) << 2;
            const int kc = kq >> 3, lo = (kq >> 2) & 1;
            float4 b4 = *reinterpret_cast<const float4*>(
                W + (size_t)(n0 + r) * K + k0 + kq);
            const int nf = r >> 3, gp = r & 7;
            uint32_t* d = Bs + (nf*4 + kc) * 66 + gp*8 + lo;
            d[0] = f2tf32(b4.x);
            d[2] = f2tf32(b4.y);
            d[4] = f2tf32(b4.z);
            d[6] = f2tf32(b4.w);
        }
        __syncthreads();

        // ---- compute: 4 kc steps x 32 mma per warp ----
        #pragma unroll
        for (int kc = 0; kc < 4; kc++) {
            uint32_t af[4][4];
            #pragma unroll
            for (int mf = 0; mf < 4; mf++) {
                const uint4 v = *reinterpret_cast<const uint4*>(
                    As + ((wm*4 + mf)*4 + kc) * 132 + lane*4);
                af[mf][0] = v.x; af[mf][1] = v.y; af[mf][2] = v.z; af[mf][3] = v.w;
            }
            uint32_t bf[8][2];
            #pragma unroll
            for (int nf = 0; nf < 8; nf++) {
                const uint2 v = *reinterpret_cast<const uint2*>(
                    Bs + ((wn*8 + nf)*4 + kc) * 66 + lane*2);
                bf[nf][0] = v.x; bf[nf][1] = v.y;
            }
            #pragma unroll
            for (int mf = 0; mf < 4; mf++)
                #pragma unroll
                for (int nf = 0; nf < 8; nf++)
                    mma_tf32(acc[mf][nf], af[mf], bf[nf]);
        }
        __syncthreads();
    }

    // ---- epilogue: bias (+relu) (+res), float2 stores ----
    #pragma unroll
    for (int mf = 0; mf < 4; mf++) {
        const int row = m0 + wm*64 + mf*16 + g;
        #pragma unroll
        for (int nf = 0; nf < 8; nf++) {
            const int col = n0 + wn*64 + nf*8 + t*2;
            const float2 bi = *reinterpret_cast<const float2*>(bias + col);
            float2 c0, c1;
            c0.x = acc[mf][nf][0] + bi.x; c0.y = acc[mf][nf][1] + bi.y;
            c1.x = acc[mf][nf][2] + bi.x; c1.y = acc[mf][nf][3] + bi.y;
            if (relu) {
                c0.x = fmaxf(c0.x, 0.f); c0.y = fmaxf(c0.y, 0.f);
                c1.x = fmaxf(c1.x, 0.f); c1.y = fmaxf(c1.y, 0.f);
            }
            const size_t b0 = (size_t)row * N + col;
            const size_t b1 = (size_t)(row + 8) * N + col;
            if (res) {
                const float2 r0 = *reinterpret_cast<const float2*>(res + b0);
                const float2 r1 = *reinterpret_cast<const float2*>(res + b1);
                c0.x += r0.x; c0.y += r0.y;
                c1.x += r1.x; c1.y += r1.y;
            }
            *reinterpret_cast<float2*>(C + b0) = c0;
            *reinterpret_cast<float2*>(C + b1) = c1;
        }
    }
}

// ---------------------------------------------------------------------------
// Tensor-core flash attention (unchanged from passing round 8)
// ---------------------------------------------------------------------------
__global__ __launch_bounds__(128, 2) void attn_tc(
    const float* __restrict__ Q, const float* __restrict__ K,
    const float* __restrict__ V, float* __restrict__ O)
{
    __shared__ uint32_t Vs [64 * 66];   // V fragment-major (k=kv, n=d)
    __shared__ uint32_t KPs[64 * 68];   // union: K frag-major / Qtmp / P row-major

    const int tid  = threadIdx.x;
    const int lane = tid & 31;
    const int w    = tid >> 5;
    const int g    = lane >> 2;
    const int t    = lane & 3;
    const int qb   = blockIdx.x;
    const int bh   = blockIdx.y;
    const int b    = bh >> 4, h = bh & 15;

    const size_t baseQ  = ((size_t)b * SS + (size_t)qb * 64) * DDIM + (size_t)h * DK;
    const size_t baseKV = (size_t)b * SS * DDIM + (size_t)h * DK;

    {
        float* qt = reinterpret_cast<float*>(KPs);
        #pragma unroll
        for (int u = 0; u < 8; u++) {
            const int f = tid + u * 128;
            const int r = f >> 4, cq = (f & 15) << 2;
            *reinterpret_cast<float4*>(qt + r*68 + cq) =
                *reinterpret_cast<const float4*>(Q + baseQ + (size_t)r * DDIM + cq);
        }
    }
    __syncthreads();

    uint32_t aq[8][4];
    {
        const float* qt = reinterpret_cast<const float*>(KPs);
        const int r0 = w*16 + g, r1 = r0 + 8;
        #pragma unroll
        for (int kc = 0; kc < 8; kc++) {
            aq[kc][0] = f2tf32(0.125f * qt[r0*68 + kc*8 + t]);
            aq[kc][1] = f2tf32(0.125f * qt[r1*68 + kc*8 + t]);
            aq[kc][2] = f2tf32(0.125f * qt[r0*68 + kc*8 + t + 4]);
            aq[kc][3] = f2tf32(0.125f * qt[r1*68 + kc*8 + t + 4]);
        }
    }

    float Of[8][4];
    float m0 = -INFINITY, m1 = -INFINITY, l0 = 0.f, l1 = 0.f;
    #pragma unroll
    for (int nf = 0; nf < 8; nf++)
        #pragma unroll
        for (int p = 0; p < 4; p++) Of[nf][p] = 0.f;

    for (int kv0 = 0; kv0 < SS; kv0 += 64) {
        __syncthreads();

        #pragma unroll
        for (int u = 0; u < 8; u++) {
            const int f = tid + u * 128;
            const int r = f >> 4;
            const int kq = (f & 15) << 2;

            {
                float4 kv4 = *reinterpret_cast<const float4*>(
                    K + baseKV + (size_t)(kv0 + r) * DDIM + kq);
                const int kc = kq >> 3, lo = (kq >> 2) & 1;
                const int nf = r >> 3, gp = r & 7;
                uint32_t* d = KPs + (nf*8 + kc) * 66 + gp*8 + lo;
                d[0] = f2tf32(kv4.x);
                d[2] = f2tf32(kv4.y);
                d[4] = f2tf32(kv4.z);
                d[6] = f2tf32(kv4.w);
            }
            {
                float4 vv4 = *reinterpret_cast<const float4*>(
                    V + baseKV + (size_t)(kv0 + r) * DDIM + kq);
                const int kc = r >> 3, kt = r & 7;
                const int tt = kt & 3, e = kt >> 2;
                const int nf = kq >> 3, gn = kq & 7;
                uint32_t* d = Vs + (nf*8 + kc) * 66 + (gn*4 + tt)*2 + e;
                d[0]  = f2tf32(vv4.x);
                d[8]  = f2tf32(vv4.y);
                d[16] = f2tf32(vv4.z);
                d[24] = f2tf32(vv4.w);
            }
        }
        __syncthreads();

        float Sf[8][4];
        #pragma unroll
        for (int nf = 0; nf < 8; nf++)
            #pragma unroll
            for (int p = 0; p < 4; p++) Sf[nf][p] = 0.f;

        #pragma unroll
        for (int kc = 0; kc < 8; kc++) {
            #pragma unroll
            for (int nf = 0; nf < 8; nf++) {
                const uint2 v = *reinterpret_cast<const uint2*>(
                    KPs + (nf*8 + kc) * 66 + lane*2);
                uint32_t bf[2] = { v.x, v.y };
                mma_tf32(Sf[nf], aq[kc], bf);
            }
        }

        float mx0 = -INFINITY, mx1 = -INFINITY;
        #pragma unroll
        for (int nf = 0; nf < 8; nf++) {
            mx0 = fmaxf(mx0, fmaxf(Sf[nf][0], Sf[nf][1]));
            mx1 = fmaxf(mx1, fmaxf(Sf[nf][2], Sf[nf][3]));
        }
        #pragma unroll
        for (int o = 1; o <= 2; o <<= 1) {
            mx0 = fmaxf(mx0, __shfl_xor_sync(0xffffffffu, mx0, o));
            mx1 = fmaxf(mx1, __shfl_xor_sync(0xffffffffu, mx1, o));
        }
        const float mn0 = fmaxf(m0, mx0), mn1 = fmaxf(m1, mx1);
        const float c0 = __expf(m0 - mn0), c1 = __expf(m1 - mn1);
        m0 = mn0; m1 = mn1;

        float s0 = 0.f, s1 = 0.f;
        #pragma unroll
        for (int nf = 0; nf < 8; nf++) {
            float p0 = __expf(Sf[nf][0] - mn0);
            float p1 = __expf(Sf[nf][1] - mn0);
            float p2 = __expf(Sf[nf][2] - mn1);
            float p3 = __expf(Sf[nf][3] - mn1);
            Sf[nf][0] = p0; Sf[nf][1] = p1; Sf[nf][2] = p2; Sf[nf][3] = p3;
            s0 += p0 + p1; s1 += p2 + p3;
        }
        #pragma unroll
        for (int o = 1; o <= 2; o <<= 1) {
            s0 += __shfl_xor_sync(0xffffffffu, s0, o);
            s1 += __shfl_xor_sync(0xffffffffu, s1, o);
        }
        l0 = l0 * c0 + s0;
        l1 = l1 * c1 + s1;
        #pragma unroll
        for (int nf = 0; nf < 8; nf++) {
            Of[nf][0] *= c0; Of[nf][1] *= c0;
            Of[nf][2] *= c1; Of[nf][3] *= c1;
        }

        __syncthreads();
        float* Pw = reinterpret_cast<float*>(KPs) + (w*16) * 68;
        #pragma unroll
        for (int nf = 0; nf < 8; nf++) {
            Pw[g*68     + nf*8 + 2*t    ] = Sf[nf][0];
            Pw[g*68     + nf*8 + 2*t + 1] = Sf[nf][1];
            Pw[(g+8)*68 + nf*8 + 2*t    ] = Sf[nf][2];
            Pw[(g+8)*68 + nf*8 + 2*t + 1] = Sf[nf][3];
        }
        __syncwarp();

        #pragma unroll
        for (int kc = 0; kc < 8; kc++) {
            uint32_t ap[4];
            ap[0] = f2tf32(Pw[g*68     + kc*8 + t    ]);
            ap[1] = f2tf32(Pw[(g+8)*68 + kc*8 + t    ]);
            ap[2] = f2tf32(Pw[g*68     + kc*8 + t + 4]);
            ap[3] = f2tf32(Pw[(g+8)*68 + kc*8 + t + 4]);
            #pragma unroll
            for (int nf = 0; nf < 8; nf++) {
                const uint2 v = *reinterpret_cast<const uint2*>(
                    Vs + (nf*8 + kc) * 66 + lane*2);
                uint32_t bf[2] = { v.x, v.y };
                mma_tf32(Of[nf], ap, bf);
            }
        }
    }

    const float inv0 = 1.0f / l0, inv1 = 1.0f / l1;
    const int r0 = w*16 + g, r1 = r0 + 8;
    #pragma unroll
    for (int nf = 0; nf < 8; nf++) {
        const int col = nf*8 + 2*t;
        float2 o0, o1;
        o0.x = Of[nf][0] * inv0; o0.y = Of[nf][1] * inv0;
        o1.x = Of[nf][2] * inv1; o1.y = Of[nf][3] * inv1;
        *reinterpret_cast<float2*>(O + baseQ + (size_t)r0 * DDIM + col) = o0;
        *reinterpret_cast<float2*>(O + baseQ + (size_t)r1 * DDIM + col) = o1;
    }
}

// ---------------------------------------------------------------------------
// Launch
// ---------------------------------------------------------------------------
extern "C" void kernel_launch(void* const* d_in, const int* in_sizes, int n_in,
                              void* d_out, int out_size)
{
    const float* x    = (const float*)d_in[0];
    const float* wq   = (const float*)d_in[1];
    const float* bq   = (const float*)d_in[2];
    const float* wk   = (const float*)d_in[3];
    const float* bk   = (const float*)d_in[4];
    const float* wv   = (const float*)d_in[5];
    const float* bv   = (const float*)d_in[6];
    const float* wo   = (const float*)d_in[7];
    const float* bo   = (const float*)d_in[8];
    const float* w1   = (const float*)d_in[9];
    const float* b1   = (const float*)d_in[10];
    const float* w2   = (const float*)d_in[11];
    const float* b2   = (const float*)d_in[12];
    const float* ln1a = (const float*)d_in[13];
    const float* ln1b = (const float*)d_in[14];
    const float* ln2a = (const float*)d_in[15];
    const float* ln2b = (const float*)d_in[16];
    float* out = (float*)d_out;

    float *xn, *q, *k, *v, *ctx, *h, *hn, *ff;
    cudaGetSymbolAddress((void**)&xn,  g_xn);
    cudaGetSymbolAddress((void**)&q,   g_q);
    cudaGetSymbolAddress((void**)&k,   g_k);
    cudaGetSymbolAddress((void**)&v,   g_v);
    cudaGetSymbolAddress((void**)&ctx, g_ctx);
    cudaGetSymbolAddress((void**)&h,   g_h);
    cudaGetSymbolAddress((void**)&hn,  g_hn);
    cudaGetSymbolAddress((void**)&ff,  g_ff);

    cudaFuncSetAttribute(gemm_tc,
        cudaFuncAttributeMaxDynamicSharedMemorySize, GEMM_SMEM_BYTES);

    const dim3 gproj(DDIM/256, MTOT/128);   // (4, 32)  = 128 CTAs
    const dim3 gffn1(FFD/256,  MTOT/128);   // (16, 32) = 512 CTAs

    ln_kernel<<<MTOT, 256>>>(x, ln1a, ln1b, xn);
    gemm_tc<<<gproj, 256, GEMM_SMEM_BYTES>>>(xn, wq, bq, nullptr, q, MTOT, DDIM, DDIM, 0);
    gemm_tc<<<gproj, 256, GEMM_SMEM_BYTES>>>(xn, wk, bk, nullptr, k, MTOT, DDIM, DDIM, 0);
    gemm_tc<<<gproj, 256, GEMM_SMEM_BYTES>>>(xn, wv, bv, nullptr, v, MTOT, DDIM, DDIM, 0);
    attn_tc<<<dim3(SS/64, BB*HH), 128>>>(q, k, v, ctx);
    gemm_tc<<<gproj, 256, GEMM_SMEM_BYTES>>>(ctx, wo, bo, x, h, MTOT, DDIM, DDIM, 0);
    ln_kernel<<<MTOT, 256>>>(h, ln2a, ln2b, hn);
    gemm_tc<<<gffn1, 256, GEMM_SMEM_BYTES>>>(hn, w1, b1, nullptr, ff, MTOT, FFD, DDIM, 1);
    gemm_tc<<<gproj, 256, GEMM_SMEM_BYTES>>>(ff, w2, b2, h, out, MTOT, DDIM, FFD, 0);
}

// round 13
// speedup vs baseline: 1.3884x; 1.3884x over previous
#include <cuda_runtime.h>
#include <cuda_fp16.h>
#include <math.h>
#include <stdint.h>

// Problem constants
#define BB   2
#define SS   2048
#define DDIM 1024
#define HH   16
#define DK   64
#define FFD  4096
#define MTOT (BB*SS)   // 4096 rows

// ---------------------------------------------------------------------------
// Scratch buffers (device globals; no runtime allocation allowed)
// ---------------------------------------------------------------------------
__device__ float g_xn [MTOT*DDIM];
__device__ float g_q  [MTOT*DDIM];
__device__ float g_k  [MTOT*DDIM];
__device__ float g_v  [MTOT*DDIM];
__device__ float g_ctx[MTOT*DDIM];
__device__ float g_h  [MTOT*DDIM];
__device__ float g_hn [MTOT*DDIM];
__device__ float g_ff [MTOT*FFD];

// ---------------------------------------------------------------------------
// LayerNorm (faithful: unbiased std, denom = sqrt(std + eps))
// ---------------------------------------------------------------------------
__global__ __launch_bounds__(256) void ln_kernel(
    const float* __restrict__ x, const float* __restrict__ alpha,
    const float* __restrict__ beta, float* __restrict__ y)
{
    const int row = blockIdx.x;
    const float4* xr = reinterpret_cast<const float4*>(x + (size_t)row * DDIM);
    float4 vv = xr[threadIdx.x];
    float s  = vv.x + vv.y + vv.z + vv.w;
    float s2 = vv.x*vv.x + vv.y*vv.y + vv.z*vv.z + vv.w*vv.w;

    __shared__ float red0[8], red1[8];
    #pragma unroll
    for (int o = 16; o; o >>= 1) {
        s  += __shfl_xor_sync(0xffffffffu, s,  o);
        s2 += __shfl_xor_sync(0xffffffffu, s2, o);
    }
    const int warp = threadIdx.x >> 5, lane = threadIdx.x & 31;
    if (lane == 0) { red0[warp] = s; red1[warp] = s2; }
    __syncthreads();
    if (threadIdx.x == 0) {
        float t = 0.f, t2 = 0.f;
        #pragma unroll
        for (int i = 0; i < 8; i++) { t += red0[i]; t2 += red1[i]; }
        red0[0] = t; red1[0] = t2;
    }
    __syncthreads();
    s = red0[0]; s2 = red1[0];

    const float mean = s * (1.0f / DDIM);
    const float var  = fmaxf(0.f, (s2 - s * mean) * (1.0f / (DDIM - 1)));  // unbiased
    const float stdv = sqrtf(var);
    const float inv  = 1.0f / sqrtf(stdv + 1e-6f);   // sqrt(std + eps) !
    const float a0 = alpha[0], b0 = beta[0];

    float4 o;
    o.x = a0 * (vv.x - mean) * inv + b0;
    o.y = a0 * (vv.y - mean) * inv + b0;
    o.z = a0 * (vv.z - mean) * inv + b0;
    o.w = a0 * (vv.w - mean) * inv + b0;
    reinterpret_cast<float4*>(y + (size_t)row * DDIM)[threadIdx.x] = o;
}

// ---------------------------------------------------------------------------
// fp16 helpers
// ---------------------------------------------------------------------------
__device__ __forceinline__ uint32_t pack_h2(float lo, float hi) {
    uint32_t r;
    asm("cvt.rn.f16x2.f32 %0, %1, %2;" : "=r"(r) : "f"(hi), "f"(lo));
    return r;
}

__device__ __forceinline__ void mma_f16(
    float c[4], const uint32_t a[4], const uint32_t b[2])
{
    asm volatile(
        "mma.sync.aligned.m16n8k16.row.col.f32.f16.f16.f32 "
        "{%0,%1,%2,%3}, {%4,%5,%6,%7}, {%8,%9}, {%0,%1,%2,%3};\n"
        : "+f"(c[0]), "+f"(c[1]), "+f"(c[2]), "+f"(c[3])
        : "r"(a[0]), "r"(a[1]), "r"(a[2]), "r"(a[3]), "r"(b[0]), "r"(b[1]));
}

// Fragment-major slot maps (u32 = f16x2 pair, p = k-pair index 0..7):
//   A block (16 m-rows x 8 pairs), 128 u32 (+4 pad): one uint4 per lane.
//   B block ( 8 n-cols x 8 pairs),  64 u32 (+2 pad): one uint2 per lane.
#define ASLOT(rr, p) ( (((rr)&7)*4 + ((p)&3))*4 + (((rr)>>3)&1) + ((((p)>>2)&1)<<1) )
#define BSLOT(n, p)  ( ((n)*8) + (((p)&3)*2) + (((p)>>2)&1) )
#define ABLK 132
#define BBLK 66

// ---------------------------------------------------------------------------
// Tensor-core GEMM (NT), fp16 m16n8k16: C = A*W^T + bias (+relu) (+res)
// CTA tile 128x128, K-tile 64 (4 k16 steps). 8 warps as 2(m)x4(n), warp
// tile 64x32 via 4(mf)x4(nf). R7-proven structure, fp16 fragments.
// Static smem: (8*4*132 + 16*4*66)*4 = 33792 B.
// ---------------------------------------------------------------------------
__global__ __launch_bounds__(256, 2) void gemm_tc(
    const float* __restrict__ A, const float* __restrict__ W,
    const float* __restrict__ bias, const float* __restrict__ res,
    float* __restrict__ C, int M, int N, int K, int relu)
{
    __shared__ uint32_t As[8*4*ABLK];    // 8 mf x 4 kc
    __shared__ uint32_t Bs[16*4*BBLK];   // 16 nf x 4 kc

    const int tid  = threadIdx.x;
    const int lane = tid & 31;
    const int warp = tid >> 5;
    const int wm = warp >> 2;          // 0..1
    const int wn = warp & 3;           // 0..3
    const int g  = lane >> 2;          // 0..7
    const int t  = lane & 3;           // 0..3
    const int m0 = blockIdx.y * 128, n0 = blockIdx.x * 128;

    float acc[4][4][4];
    #pragma unroll
    for (int i = 0; i < 4; i++)
        #pragma unroll
        for (int j = 0; j < 4; j++)
            #pragma unroll
            for (int p = 0; p < 4; p++) acc[i][j][p] = 0.f;

    for (int k0 = 0; k0 < K; k0 += 64) {
        // ---- fill: 128 rows x 16 float4 per operand = 8 slots/thread each ----
        #pragma unroll
        for (int u = 0; u < 8; u++) {
            const int f  = tid + (u << 8);
            const int r  = f >> 4;              // 0..127
            const int kq = (f & 15) << 2;       // 0..60 step 4
            const int kc = kq >> 4;
            const int p0 = (kq & 15) >> 1;      // 0,2,4,6

            {   // A
                const float4 a4 = *reinterpret_cast<const float4*>(
                    A + (size_t)(m0 + r) * K + k0 + kq);
                uint32_t* d = As + ((r >> 4) * 4 + kc) * ABLK;
                d[ASLOT(r & 15, p0)]     = pack_h2(a4.x, a4.y);
                d[ASLOT(r & 15, p0 + 1)] = pack_h2(a4.z, a4.w);
            }
            {   // B
                const float4 b4 = *reinterpret_cast<const float4*>(
                    W + (size_t)(n0 + r) * K + k0 + kq);
                uint32_t* d = Bs + ((r >> 3) * 4 + kc) * BBLK;
                d[BSLOT(r & 7, p0)]     = pack_h2(b4.x, b4.y);
                d[BSLOT(r & 7, p0 + 1)] = pack_h2(b4.z, b4.w);
            }
        }
        __syncthreads();

        // ---- compute: 4 kc steps x 16 mma per warp ----
        #pragma unroll
        for (int kc = 0; kc < 4; kc++) {
            uint32_t af[4][4];
            #pragma unroll
            for (int mf = 0; mf < 4; mf++) {
                const uint4 v = *reinterpret_cast<const uint4*>(
                    As + ((wm*4 + mf)*4 + kc) * ABLK + lane*4);
                af[mf][0] = v.x; af[mf][1] = v.y; af[mf][2] = v.z; af[mf][3] = v.w;
            }
            uint32_t bf[4][2];
            #pragma unroll
            for (int nf = 0; nf < 4; nf++) {
                const uint2 v = *reinterpret_cast<const uint2*>(
                    Bs + ((wn*4 + nf)*4 + kc) * BBLK + lane*2);
                bf[nf][0] = v.x; bf[nf][1] = v.y;
            }
            #pragma unroll
            for (int mf = 0; mf < 4; mf++)
                #pragma unroll
                for (int nf = 0; nf < 4; nf++)
                    mma_f16(acc[mf][nf], af[mf], bf[nf]);
        }
        __syncthreads();
    }

    // ---- epilogue: bias (+relu) (+res), float2 stores ----
    #pragma unroll
    for (int mf = 0; mf < 4; mf++) {
        const int row = m0 + wm*64 + mf*16 + g;
        #pragma unroll
        for (int nf = 0; nf < 4; nf++) {
            const int col = n0 + wn*32 + nf*8 + t*2;
            const float2 bi = *reinterpret_cast<const float2*>(bias + col);
            float2 c0, c1;
            c0.x = acc[mf][nf][0] + bi.x; c0.y = acc[mf][nf][1] + bi.y;
            c1.x = acc[mf][nf][2] + bi.x; c1.y = acc[mf][nf][3] + bi.y;
            if (relu) {
                c0.x = fmaxf(c0.x, 0.f); c0.y = fmaxf(c0.y, 0.f);
                c1.x = fmaxf(c1.x, 0.f); c1.y = fmaxf(c1.y, 0.f);
            }
            const size_t b0 = (size_t)row * N + col;
            const size_t b1 = (size_t)(row + 8) * N + col;
            if (res) {
                const float2 r0 = *reinterpret_cast<const float2*>(res + b0);
                const float2 r1 = *reinterpret_cast<const float2*>(res + b1);
                c0.x += r0.x; c0.y += r0.y;
                c1.x += r1.x; c1.y += r1.y;
            }
            *reinterpret_cast<float2*>(C + b0) = c0;
            *reinterpret_cast<float2*>(C + b1) = c1;
        }
    }
}

// ---------------------------------------------------------------------------
// Tensor-core flash attention, fp16 m16n8k16 (structure from passing R8).
// Br=Bc=64, 4 warps x 16 q-rows. Q fragments in registers (1/8 folded).
// K,V fragment-major fp16 smem; P via f32 smem roundtrip aliased over K.
// ---------------------------------------------------------------------------
__global__ __launch_bounds__(128, 2) void attn_tc(
    const float* __restrict__ Q, const float* __restrict__ K,
    const float* __restrict__ V, float* __restrict__ O)
{
    __shared__ uint32_t Vs [8*4*BBLK];   // V frag-major (k=kv, n=d): 2112 u32
    __shared__ uint32_t KPs[64 * 68];    // union: K frag (2112) / Qtmp / P f32

    const int tid  = threadIdx.x;
    const int lane = tid & 31;
    const int w    = tid >> 5;
    const int g    = lane >> 2;
    const int t    = lane & 3;
    const int qb   = blockIdx.x;
    const int bh   = blockIdx.y;
    const int b    = bh >> 4, h = bh & 15;

    const size_t baseQ  = ((size_t)b * SS + (size_t)qb * 64) * DDIM + (size_t)h * DK;
    const size_t baseKV = (size_t)b * SS * DDIM + (size_t)h * DK;

    // ---- stage Q row-major, lift fp16 fragments to registers ----
    {
        float* qt = reinterpret_cast<float*>(KPs);
        #pragma unroll
        for (int u = 0; u < 8; u++) {
            const int f = tid + u * 128;
            const int r = f >> 4, cq = (f & 15) << 2;
            *reinterpret_cast<float4*>(qt + r*68 + cq) =
                *reinterpret_cast<const float4*>(Q + baseQ + (size_t)r * DDIM + cq);
        }
    }
    __syncthreads();

    uint32_t aq[4][4];
    {
        const float* qt = reinterpret_cast<const float*>(KPs);
        const int r0 = w*16 + g, r1 = r0 + 8;
        #pragma unroll
        for (int kc = 0; kc < 4; kc++) {
            const int k = kc*16 + 2*t;
            aq[kc][0] = pack_h2(0.125f*qt[r0*68 + k],     0.125f*qt[r0*68 + k + 1]);
            aq[kc][1] = pack_h2(0.125f*qt[r1*68 + k],     0.125f*qt[r1*68 + k + 1]);
            aq[kc][2] = pack_h2(0.125f*qt[r0*68 + k + 8], 0.125f*qt[r0*68 + k + 9]);
            aq[kc][3] = pack_h2(0.125f*qt[r1*68 + k + 8], 0.125f*qt[r1*68 + k + 9]);
        }
    }

    float Of[8][4];
    float m0 = -INFINITY, m1 = -INFINITY, l0 = 0.f, l1 = 0.f;
    #pragma unroll
    for (int nf = 0; nf < 8; nf++)
        #pragma unroll
        for (int p = 0; p < 4; p++) Of[nf][p] = 0.f;

    for (int kv0 = 0; kv0 < SS; kv0 += 64) {
        __syncthreads();   // Q staging / previous tile's P+V reads complete

        // ---- fill K (B-frag: n=kv, k=d) and V (B-frag: k=kv, n=d) ----
        #pragma unroll
        for (int u = 0; u < 8; u++) {
            const int f = tid + u * 128;
            const int r = f >> 4;               // kv row 0..63
            const int kq = (f & 15) << 2;       // d col 0..60 step 4

            {   // K: block (nf=r>>3, kc=kq>>4), full pairs from this float4
                const float4 k4 = *reinterpret_cast<const float4*>(
                    K + baseKV + (size_t)(kv0 + r) * DDIM + kq);
                const int p0 = (kq & 15) >> 1;
                uint32_t* d = KPs + ((r >> 3) * 4 + (kq >> 4)) * BBLK;
                d[BSLOT(r & 7, p0)]     = pack_h2(k4.x, k4.y);
                d[BSLOT(r & 7, p0 + 1)] = pack_h2(k4.z, k4.w);
            }
            {   // V: k = kv = r (half position r&1), n = d cols
                const float4 v4 = *reinterpret_cast<const float4*>(
                    V + baseKV + (size_t)(kv0 + r) * DDIM + kq);
                const int kc = r >> 4, p = (r & 15) >> 1, e = r & 1;
                __half* vh = reinterpret_cast<__half*>(Vs);
                const float vals[4] = { v4.x, v4.y, v4.z, v4.w };
                #pragma unroll
                for (int j = 0; j < 4; j++) {
                    const int c = kq + j;
                    const int slot = ((c >> 3) * 4 + kc) * BBLK + BSLOT(c & 7, p);
                    vh[slot*2 + e] = __float2half_rn(vals[j]);
                }
            }
        }
        __syncthreads();

        // ---- S = (Q/8) K^T : 32 mma per warp ----
        float Sf[8][4];
        #pragma unroll
        for (int nf = 0; nf < 8; nf++)
            #pragma unroll
            for (int p = 0; p < 4; p++) Sf[nf][p] = 0.f;

        #pragma unroll
        for (int kc = 0; kc < 4; kc++) {
            #pragma unroll
            for (int nf = 0; nf < 8; nf++) {
                const uint2 v = *reinterpret_cast<const uint2*>(
                    KPs + (nf*4 + kc) * BBLK + lane*2);
                uint32_t bf[2] = { v.x, v.y };
                mma_f16(Sf[nf], aq[kc], bf);
            }
        }

        // ---- online softmax ----
        float mx0 = -INFINITY, mx1 = -INFINITY;
        #pragma unroll
        for (int nf = 0; nf < 8; nf++) {
            mx0 = fmaxf(mx0, fmaxf(Sf[nf][0], Sf[nf][1]));
            mx1 = fmaxf(mx1, fmaxf(Sf[nf][2], Sf[nf][3]));
        }
        #pragma unroll
        for (int o = 1; o <= 2; o <<= 1) {
            mx0 = fmaxf(mx0, __shfl_xor_sync(0xffffffffu, mx0, o));
            mx1 = fmaxf(mx1, __shfl_xor_sync(0xffffffffu, mx1, o));
        }
        const float mn0 = fmaxf(m0, mx0), mn1 = fmaxf(m1, mx1);
        const float c0 = __expf(m0 - mn0), c1 = __expf(m1 - mn1);
        m0 = mn0; m1 = mn1;

        float s0 = 0.f, s1 = 0.f;
        #pragma unroll
        for (int nf = 0; nf < 8; nf++) {
            float p0 = __expf(Sf[nf][0] - mn0);
            float p1 = __expf(Sf[nf][1] - mn0);
            float p2 = __expf(Sf[nf][2] - mn1);
            float p3 = __expf(Sf[nf][3] - mn1);
            Sf[nf][0] = p0; Sf[nf][1] = p1; Sf[nf][2] = p2; Sf[nf][3] = p3;
            s0 += p0 + p1; s1 += p2 + p3;
        }
        #pragma unroll
        for (int o = 1; o <= 2; o <<= 1) {
            s0 += __shfl_xor_sync(0xffffffffu, s0, o);
            s1 += __shfl_xor_sync(0xffffffffu, s1, o);
        }
        l0 = l0 * c0 + s0;
        l1 = l1 * c1 + s1;
        #pragma unroll
        for (int nf = 0; nf < 8; nf++) {
            Of[nf][0] *= c0; Of[nf][1] *= c0;
            Of[nf][2] *= c1; Of[nf][3] *= c1;
        }

        // ---- P -> smem f32 (aliased over K) ----
        __syncthreads();
        float* Pw = reinterpret_cast<float*>(KPs) + (w*16) * 68;
        #pragma unroll
        for (int nf = 0; nf < 8; nf++) {
            Pw[g*68     + nf*8 + 2*t    ] = Sf[nf][0];
            Pw[g*68     + nf*8 + 2*t + 1] = Sf[nf][1];
            Pw[(g+8)*68 + nf*8 + 2*t    ] = Sf[nf][2];
            Pw[(g+8)*68 + nf*8 + 2*t + 1] = Sf[nf][3];
        }
        __syncwarp();

        // ---- O += P V : 32 mma per warp ----
        #pragma unroll
        for (int kc = 0; kc < 4; kc++) {
            const int k = kc*16 + 2*t;
            uint32_t ap[4];
            ap[0] = pack_h2(Pw[g*68     + k],     Pw[g*68     + k + 1]);
            ap[1] = pack_h2(Pw[(g+8)*68 + k],     Pw[(g+8)*68 + k + 1]);
            ap[2] = pack_h2(Pw[g*68     + k + 8], Pw[g*68     + k + 9]);
            ap[3] = pack_h2(Pw[(g+8)*68 + k + 8], Pw[(g+8)*68 + k + 9]);
            #pragma unroll
            for (int nf = 0; nf < 8; nf++) {
                const uint2 v = *reinterpret_cast<const uint2*>(
                    Vs + (nf*4 + kc) * BBLK + lane*2);
                uint32_t bf[2] = { v.x, v.y };
                mma_f16(Of[nf], ap, bf);
            }
        }
    }

    // ---- finalize: divide by l, store ctx head slice ----
    const float inv0 = 1.0f / l0, inv1 = 1.0f / l1;
    const int r0 = w*16 + g, r1 = r0 + 8;
    #pragma unroll
    for (int nf = 0; nf < 8; nf++) {
        const int col = nf*8 + 2*t;
        float2 o0, o1;
        o0.x = Of[nf][0] * inv0; o0.y = Of[nf][1] * inv0;
        o1.x = Of[nf][2] * inv1; o1.y = Of[nf][3] * inv1;
        *reinterpret_cast<float2*>(O + baseQ + (size_t)r0 * DDIM + col) = o0;
        *reinterpret_cast<float2*>(O + baseQ + (size_t)r1 * DDIM + col) = o1;
    }
}

// ---------------------------------------------------------------------------
// Launch
// ---------------------------------------------------------------------------
extern "C" void kernel_launch(void* const* d_in, const int* in_sizes, int n_in,
                              void* d_out, int out_size)
{
    const float* x    = (const float*)d_in[0];
    const float* wq   = (const float*)d_in[1];
    const float* bq   = (const float*)d_in[2];
    const float* wk   = (const float*)d_in[3];
    const float* bk   = (const float*)d_in[4];
    const float* wv   = (const float*)d_in[5];
    const float* bv   = (const float*)d_in[6];
    const float* wo   = (const float*)d_in[7];
    const float* bo   = (const float*)d_in[8];
    const float* w1   = (const float*)d_in[9];
    const float* b1   = (const float*)d_in[10];
    const float* w2   = (const float*)d_in[11];
    const float* b2   = (const float*)d_in[12];
    const float* ln1a = (const float*)d_in[13];
    const float* ln1b = (const float*)d_in[14];
    const float* ln2a = (const float*)d_in[15];
    const float* ln2b = (const float*)d_in[16];
    float* out = (float*)d_out;

    float *xn, *q, *k, *v, *ctx, *h, *hn, *ff;
    cudaGetSymbolAddress((void**)&xn,  g_xn);
    cudaGetSymbolAddress((void**)&q,   g_q);
    cudaGetSymbolAddress((void**)&k,   g_k);
    cudaGetSymbolAddress((void**)&v,   g_v);
    cudaGetSymbolAddress((void**)&ctx, g_ctx);
    cudaGetSymbolAddress((void**)&h,   g_h);
    cudaGetSymbolAddress((void**)&hn,  g_hn);
    cudaGetSymbolAddress((void**)&ff,  g_ff);

    const dim3 gproj(DDIM/128, MTOT/128);   // (8, 32)
    const dim3 gffn1(FFD/128,  MTOT/128);   // (32, 32)

    ln_kernel<<<MTOT, 256>>>(x, ln1a, ln1b, xn);
    gemm_tc<<<gproj, 256>>>(xn, wq, bq, nullptr, q, MTOT, DDIM, DDIM, 0);
    gemm_tc<<<gproj, 256>>>(xn, wk, bk, nullptr, k, MTOT, DDIM, DDIM, 0);
    gemm_tc<<<gproj, 256>>>(xn, wv, bv, nullptr, v, MTOT, DDIM, DDIM, 0);
    attn_tc<<<dim3(SS/64, BB*HH), 128>>>(q, k, v, ctx);
    gemm_tc<<<gproj, 256>>>(ctx, wo, bo, x, h, MTOT, DDIM, DDIM, 0);
    ln_kernel<<<MTOT, 256>>>(h, ln2a, ln2b, hn);
    gemm_tc<<<gffn1, 256>>>(hn, w1, b1, nullptr, ff, MTOT, FFD, DDIM, 1);
    gemm_tc<<<gproj, 256>>>(ff, w2, b2, h, out, MTOT, DDIM, FFD, 0);
}

// round 14
// speedup vs baseline: 2.1486x; 1.5475x over previous
#include <cuda_runtime.h>
#include <cuda_fp16.h>
#include <math.h>
#include <stdint.h>

// Problem constants
#define BB   2
#define SS   2048
#define DDIM 1024
#define HH   16
#define DK   64
#define FFD  4096
#define MTOT (BB*SS)   // 4096 rows

// ---------------------------------------------------------------------------
// Scratch buffers (device globals; no runtime allocation allowed)
// ---------------------------------------------------------------------------
__device__ float    g_q  [MTOT*DDIM];
__device__ float    g_k  [MTOT*DDIM];
__device__ float    g_v  [MTOT*DDIM];
__device__ float    g_h  [MTOT*DDIM];
// fp16 fragment-major activation buffers (u32 = packed f16x2)
__device__ uint32_t g_xn16 [MTOT*DDIM/2];
__device__ uint32_t g_ctx16[MTOT*DDIM/2];
__device__ uint32_t g_hn16 [MTOT*DDIM/2];
__device__ uint32_t g_ff16 [MTOT*FFD/2];
// fp16 fragment-major weights
__device__ uint32_t g_wq16[DDIM*DDIM/2];
__device__ uint32_t g_wk16[DDIM*DDIM/2];
__device__ uint32_t g_wv16[DDIM*DDIM/2];
__device__ uint32_t g_wo16[DDIM*DDIM/2];
__device__ uint32_t g_w116[FFD*DDIM/2];
__device__ uint32_t g_w216[DDIM*FFD/2];

// ---------------------------------------------------------------------------
// fp16 helpers + fragment-major layout (validated in R13; pads removed)
// ---------------------------------------------------------------------------
__device__ __forceinline__ uint32_t pack_h2(float lo, float hi) {
    uint32_t r;
    asm("cvt.rn.f16x2.f32 %0, %1, %2;" : "=r"(r) : "f"(hi), "f"(lo));
    return r;
}

__device__ __forceinline__ void mma_f16(
    float c[4], const uint32_t a[4], const uint32_t b[2])
{
    asm volatile(
        "mma.sync.aligned.m16n8k16.row.col.f32.f16.f16.f32 "
        "{%0,%1,%2,%3}, {%4,%5,%6,%7}, {%8,%9}, {%0,%1,%2,%3};\n"
        : "+f"(c[0]), "+f"(c[1]), "+f"(c[2]), "+f"(c[3])
        : "r"(a[0]), "r"(a[1]), "r"(a[2]), "r"(a[3]), "r"(b[0]), "r"(b[1]));
}

// slot maps inside a fragment block (p = k-pair index 0..7 within 16 k)
#define ASLOT(rr, p) ( (((rr)&7)*4 + ((p)&3))*4 + (((rr)>>3)&1) + ((((p)>>2)&1)<<1) )
#define BSLOT(n, p)  ( ((n)*8) + (((p)&3)*2) + (((p)>>2)&1) )

// Global fragment-major index (u32 units).
// A layout: [mb][kt][mf(8)*4+kc][128]; B layout: [nb][kt][nf(16)*4+kc][64]
__device__ __forceinline__ int a_idx(int R, int k, int K) {
    const int mb = R >> 7, rl = R & 127, mf = rl >> 4, rr = rl & 15;
    const int kt = k >> 6, kc = (k >> 4) & 3, p = (k & 15) >> 1;
    return ((mb * (K >> 6) + kt) * 32 + mf*4 + kc) * 128 + ASLOT(rr, p);
}
__device__ __forceinline__ int b_idx(int n, int k, int K) {
    const int nb = n >> 7, nl = n & 127, nf = nl >> 3, nn = nl & 7;
    const int kt = k >> 6, kc = (k >> 4) & 3, p = (k & 15) >> 1;
    return ((nb * (K >> 6) + kt) * 64 + nf*4 + kc) * 64 + BSLOT(nn, p);
}

// ---------------------------------------------------------------------------
// Weight converter: W[N,K] f32 row-major -> fp16 B-fragment-major.
// One thread per (n, 16-wide k chunk).
// ---------------------------------------------------------------------------
__global__ __launch_bounds__(256) void conv_b(
    const float* __restrict__ W, uint32_t* __restrict__ out, int N, int K)
{
    const int t  = blockIdx.x * 256 + threadIdx.x;
    const int nk = K >> 4;
    if (t >= N * nk) return;
    const int n = t / nk, k0 = (t % nk) << 4;
    float w[16];
    const float4* wp = reinterpret_cast<const float4*>(W + (size_t)n * K + k0);
    *reinterpret_cast<float4*>(w)      = wp[0];
    *reinterpret_cast<float4*>(w + 4)  = wp[1];
    *reinterpret_cast<float4*>(w + 8)  = wp[2];
    *reinterpret_cast<float4*>(w + 12) = wp[3];
    uint32_t* d = out + b_idx(n, k0, K);   // slot offset (p&3)*2+(p>>2) rel. to p=0
    d[0] = pack_h2(w[0],  w[1]);
    d[2] = pack_h2(w[2],  w[3]);
    d[4] = pack_h2(w[4],  w[5]);
    d[6] = pack_h2(w[6],  w[7]);
    d[1] = pack_h2(w[8],  w[9]);
    d[3] = pack_h2(w[10], w[11]);
    d[5] = pack_h2(w[12], w[13]);
    d[7] = pack_h2(w[14], w[15]);
}

// ---------------------------------------------------------------------------
// LayerNorm (faithful math) -> fp16 A-fragment-major output
// ---------------------------------------------------------------------------
__global__ __launch_bounds__(256) void ln_kernel(
    const float* __restrict__ x, const float* __restrict__ alpha,
    const float* __restrict__ beta, uint32_t* __restrict__ y16)
{
    const int row = blockIdx.x;
    const float4* xr = reinterpret_cast<const float4*>(x + (size_t)row * DDIM);
    float4 vv = xr[threadIdx.x];
    float s  = vv.x + vv.y + vv.z + vv.w;
    float s2 = vv.x*vv.x + vv.y*vv.y + vv.z*vv.z + vv.w*vv.w;

    __shared__ float red0[8], red1[8];
    #pragma unroll
    for (int o = 16; o; o >>= 1) {
        s  += __shfl_xor_sync(0xffffffffu, s,  o);
        s2 += __shfl_xor_sync(0xffffffffu, s2, o);
    }
    const int warp = threadIdx.x >> 5, lane = threadIdx.x & 31;
    if (lane == 0) { red0[warp] = s; red1[warp] = s2; }
    __syncthreads();
    if (threadIdx.x == 0) {
        float t = 0.f, t2 = 0.f;
        #pragma unroll
        for (int i = 0; i < 8; i++) { t += red0[i]; t2 += red1[i]; }
        red0[0] = t; red1[0] = t2;
    }
    __syncthreads();
    s = red0[0]; s2 = red1[0];

    const float mean = s * (1.0f / DDIM);
    const float var  = fmaxf(0.f, (s2 - s * mean) * (1.0f / (DDIM - 1)));  // unbiased
    const float stdv = sqrtf(var);
    const float inv  = 1.0f / sqrtf(stdv + 1e-6f);   // sqrt(std + eps) !
    const float a0 = alpha[0], b0 = beta[0];

    const int kq = threadIdx.x * 4;
    float o0 = a0 * (vv.x - mean) * inv + b0;
    float o1 = a0 * (vv.y - mean) * inv + b0;
    float o2 = a0 * (vv.z - mean) * inv + b0;
    float o3 = a0 * (vv.w - mean) * inv + b0;
    const int a = a_idx(row, kq, DDIM);
    y16[a]     = pack_h2(o0, o1);
    y16[a + 4] = pack_h2(o2, o3);   // p -> p+1 is +4 within the block
}

// ---------------------------------------------------------------------------
// fp16 GEMM (NT) with frag-major global operands + cp.async 2-stage pipeline.
// C[M,N] = A*W^T + bias, optional relu / residual.  Out: f32 (Cf) or
// fp16 A-fragment-major (Ch, for chaining into the next GEMM).
// CTA 128x128, K-tile 64; 8 warps 2(m)x4(n), warp tile 64x32 (4x4 frags).
// Dynamic smem: 2 stages x 8192 u32 = 65536 B.
// ---------------------------------------------------------------------------
#define GEMM_DSMEM 65536

__global__ __launch_bounds__(256, 2) void gemm_h(
    const uint32_t* __restrict__ Af, const uint32_t* __restrict__ Bf,
    const float* __restrict__ bias, const float* __restrict__ res,
    float* __restrict__ Cf, uint32_t* __restrict__ Ch,
    int M, int N, int K, int relu)
{
    extern __shared__ uint32_t sm[];

    const int tid  = threadIdx.x;
    const int lane = tid & 31;
    const int warp = tid >> 5;
    const int wm = warp >> 2;          // 0..1
    const int wn = warp & 3;           // 0..3
    const int g  = lane >> 2;          // 0..7
    const int t  = lane & 3;           // 0..3
    const int mb = blockIdx.y, nb = blockIdx.x;
    const int ktN = K >> 6;

    const uint32_t smb = (uint32_t)__cvta_generic_to_shared(sm);

    float acc[4][4][4];
    #pragma unroll
    for (int i = 0; i < 4; i++)
        #pragma unroll
        for (int j = 0; j < 4; j++)
            #pragma unroll
            for (int p = 0; p < 4; p++) acc[i][j][p] = 0.f;

    // --- async copy of one k-tile (A: 4096 u32, B: 4096 u32) into stage s ---
    auto issue = [&](int kt, int s) {
        const uint32_t* sa = Af + (size_t)(mb * ktN + kt) * 4096;
        const uint32_t* sb = Bf + (size_t)(nb * ktN + kt) * 4096;
        const uint32_t da = smb + s * 32768;
        #pragma unroll
        for (int j = 0; j < 4; j++) {
            const int c = tid + j * 256;
            asm volatile("cp.async.cg.shared.global [%0], [%1], 16;"
                :: "r"(da + c*16), "l"(sa + c*4));
        }
        #pragma unroll
        for (int j = 0; j < 4; j++) {
            const int c = tid + j * 256;
            asm volatile("cp.async.cg.shared.global [%0], [%1], 16;"
                :: "r"(da + 16384 + c*16), "l"(sb + c*4));
        }
        asm volatile("cp.async.commit_group;" ::: "memory");
    };

    issue(0, 0);
    for (int kt = 0; kt < ktN; kt++) {
        const int s = kt & 1;
        if (kt + 1 < ktN) {
            issue(kt + 1, s ^ 1);
            asm volatile("cp.async.wait_group 1;" ::: "memory");
        } else {
            asm volatile("cp.async.wait_group 0;" ::: "memory");
        }
        __syncthreads();

        const uint32_t* As = sm + s * 8192;
        const uint32_t* Bs = As + 4096;
        #pragma unroll
        for (int kc = 0; kc < 4; kc++) {
            uint32_t af[4][4];
            #pragma unroll
            for (int mf = 0; mf < 4; mf++) {
                const uint4 v = *reinterpret_cast<const uint4*>(
                    As + ((wm*4 + mf)*4 + kc) * 128 + lane*4);
                af[mf][0] = v.x; af[mf][1] = v.y; af[mf][2] = v.z; af[mf][3] = v.w;
            }
            uint32_t bf[4][2];
            #pragma unroll
            for (int nf = 0; nf < 4; nf++) {
                const uint2 v = *reinterpret_cast<const uint2*>(
                    Bs + ((wn*4 + nf)*4 + kc) * 64 + lane*2);
                bf[nf][0] = v.x; bf[nf][1] = v.y;
            }
            #pragma unroll
            for (int mf = 0; mf < 4; mf++)
                #pragma unroll
                for (int nf = 0; nf < 4; nf++)
                    mma_f16(acc[mf][nf], af[mf], bf[nf]);
        }
        __syncthreads();   // stage s free for issue(kt+2)
    }

    // ---- epilogue ----
    #pragma unroll
    for (int mf = 0; mf < 4; mf++) {
        const int row = mb*128 + wm*64 + mf*16 + g;
        #pragma unroll
        for (int nf = 0; nf < 4; nf++) {
            const int col = nb*128 + wn*32 + nf*8 + t*2;
            const float2 bi = *reinterpret_cast<const float2*>(bias + col);
            float2 c0, c1;
            c0.x = acc[mf][nf][0] + bi.x; c0.y = acc[mf][nf][1] + bi.y;
            c1.x = acc[mf][nf][2] + bi.x; c1.y = acc[mf][nf][3] + bi.y;
            if (relu) {
                c0.x = fmaxf(c0.x, 0.f); c0.y = fmaxf(c0.y, 0.f);
                c1.x = fmaxf(c1.x, 0.f); c1.y = fmaxf(c1.y, 0.f);
            }
            if (Ch) {   // fp16 fragment-major chain output
                Ch[a_idx(row,     col, N)] = pack_h2(c0.x, c0.y);
                Ch[a_idx(row + 8, col, N)] = pack_h2(c1.x, c1.y);
            } else {
                const size_t b0 = (size_t)row * N + col;
                const size_t b1 = (size_t)(row + 8) * N + col;
                if (res) {
                    const float2 r0 = *reinterpret_cast<const float2*>(res + b0);
                    const float2 r1 = *reinterpret_cast<const float2*>(res + b1);
                    c0.x += r0.x; c0.y += r0.y;
                    c1.x += r1.x; c1.y += r1.y;
                }
                *reinterpret_cast<float2*>(Cf + b0) = c0;
                *reinterpret_cast<float2*>(Cf + b1) = c1;
            }
        }
    }
}

// ---------------------------------------------------------------------------
// Tensor-core flash attention, fp16 m16n8k16 (R13-passing structure);
// output written as fp16 A-fragment-major (ctx16).
// ---------------------------------------------------------------------------
#define BBLK 66
#define BSLOTP(n, p)  ( ((n)*8) + (((p)&3)*2) + (((p)>>2)&1) )

__global__ __launch_bounds__(128, 2) void attn_tc(
    const float* __restrict__ Q, const float* __restrict__ K,
    const float* __restrict__ V, uint32_t* __restrict__ ctx16)
{
    __shared__ uint32_t Vs [8*4*BBLK];
    __shared__ uint32_t KPs[64 * 68];

    const int tid  = threadIdx.x;
    const int lane = tid & 31;
    const int w    = tid >> 5;
    const int g    = lane >> 2;
    const int t    = lane & 3;
    const int qb   = blockIdx.x;
    const int bh   = blockIdx.y;
    const int b    = bh >> 4, h = bh & 15;

    const size_t baseQ  = ((size_t)b * SS + (size_t)qb * 64) * DDIM + (size_t)h * DK;
    const size_t baseKV = (size_t)b * SS * DDIM + (size_t)h * DK;

    {
        float* qt = reinterpret_cast<float*>(KPs);
        #pragma unroll
        for (int u = 0; u < 8; u++) {
            const int f = tid + u * 128;
            const int r = f >> 4, cq = (f & 15) << 2;
            *reinterpret_cast<float4*>(qt + r*68 + cq) =
                *reinterpret_cast<const float4*>(Q + baseQ + (size_t)r * DDIM + cq);
        }
    }
    __syncthreads();

    uint32_t aq[4][4];
    {
        const float* qt = reinterpret_cast<const float*>(KPs);
        const int r0 = w*16 + g, r1 = r0 + 8;
        #pragma unroll
        for (int kc = 0; kc < 4; kc++) {
            const int k = kc*16 + 2*t;
            aq[kc][0] = pack_h2(0.125f*qt[r0*68 + k],     0.125f*qt[r0*68 + k + 1]);
            aq[kc][1] = pack_h2(0.125f*qt[r1*68 + k],     0.125f*qt[r1*68 + k + 1]);
            aq[kc][2] = pack_h2(0.125f*qt[r0*68 + k + 8], 0.125f*qt[r0*68 + k + 9]);
            aq[kc][3] = pack_h2(0.125f*qt[r1*68 + k + 8], 0.125f*qt[r1*68 + k + 9]);
        }
    }

    float Of[8][4];
    float m0 = -INFINITY, m1 = -INFINITY, l0 = 0.f, l1 = 0.f;
    #pragma unroll
    for (int nf = 0; nf < 8; nf++)
        #pragma unroll
        for (int p = 0; p < 4; p++) Of[nf][p] = 0.f;

    for (int kv0 = 0; kv0 < SS; kv0 += 64) {
        __syncthreads();

        #pragma unroll
        for (int u = 0; u < 8; u++) {
            const int f = tid + u * 128;
            const int r = f >> 4;
            const int kq = (f & 15) << 2;

            {
                const float4 k4 = *reinterpret_cast<const float4*>(
                    K + baseKV + (size_t)(kv0 + r) * DDIM + kq);
                const int p0 = (kq & 15) >> 1;
                uint32_t* d = KPs + ((r >> 3) * 4 + (kq >> 4)) * BBLK;
                d[BSLOTP(r & 7, p0)]     = pack_h2(k4.x, k4.y);
                d[BSLOTP(r & 7, p0 + 1)] = pack_h2(k4.z, k4.w);
            }
            {
                const float4 v4 = *reinterpret_cast<const float4*>(
                    V + baseKV + (size_t)(kv0 + r) * DDIM + kq);
                const int kc = r >> 4, p = (r & 15) >> 1, e = r & 1;
                __half* vh = reinterpret_cast<__half*>(Vs);
                const float vals[4] = { v4.x, v4.y, v4.z, v4.w };
                #pragma unroll
                for (int j = 0; j < 4; j++) {
                    const int c = kq + j;
                    const int slot = ((c >> 3) * 4 + kc) * BBLK + BSLOTP(c & 7, p);
                    vh[slot*2 + e] = __float2half_rn(vals[j]);
                }
            }
        }
        __syncthreads();

        float Sf[8][4];
        #pragma unroll
        for (int nf = 0; nf < 8; nf++)
            #pragma unroll
            for (int p = 0; p < 4; p++) Sf[nf][p] = 0.f;

        #pragma unroll
        for (int kc = 0; kc < 4; kc++) {
            #pragma unroll
            for (int nf = 0; nf < 8; nf++) {
                const uint2 v = *reinterpret_cast<const uint2*>(
                    KPs + (nf*4 + kc) * BBLK + lane*2);
                uint32_t bf[2] = { v.x, v.y };
                mma_f16(Sf[nf], aq[kc], bf);
            }
        }

        float mx0 = -INFINITY, mx1 = -INFINITY;
        #pragma unroll
        for (int nf = 0; nf < 8; nf++) {
            mx0 = fmaxf(mx0, fmaxf(Sf[nf][0], Sf[nf][1]));
            mx1 = fmaxf(mx1, fmaxf(Sf[nf][2], Sf[nf][3]));
        }
        #pragma unroll
        for (int o = 1; o <= 2; o <<= 1) {
            mx0 = fmaxf(mx0, __shfl_xor_sync(0xffffffffu, mx0, o));
            mx1 = fmaxf(mx1, __shfl_xor_sync(0xffffffffu, mx1, o));
        }
        const float mn0 = fmaxf(m0, mx0), mn1 = fmaxf(m1, mx1);
        const float c0 = __expf(m0 - mn0), c1 = __expf(m1 - mn1);
        m0 = mn0; m1 = mn1;

        float s0 = 0.f, s1 = 0.f;
        #pragma unroll
        for (int nf = 0; nf < 8; nf++) {
            float p0 = __expf(Sf[nf][0] - mn0);
            float p1 = __expf(Sf[nf][1] - mn0);
            float p2 = __expf(Sf[nf][2] - mn1);
            float p3 = __expf(Sf[nf][3] - mn1);
            Sf[nf][0] = p0; Sf[nf][1] = p1; Sf[nf][2] = p2; Sf[nf][3] = p3;
            s0 += p0 + p1; s1 += p2 + p3;
        }
        #pragma unroll
        for (int o = 1; o <= 2; o <<= 1) {
            s0 += __shfl_xor_sync(0xffffffffu, s0, o);
            s1 += __shfl_xor_sync(0xffffffffu, s1, o);
        }
        l0 = l0 * c0 + s0;
        l1 = l1 * c1 + s1;
        #pragma unroll
        for (int nf = 0; nf < 8; nf++) {
            Of[nf][0] *= c0; Of[nf][1] *= c0;
            Of[nf][2] *= c1; Of[nf][3] *= c1;
        }

        __syncthreads();
        float* Pw = reinterpret_cast<float*>(KPs) + (w*16) * 68;
        #pragma unroll
        for (int nf = 0; nf < 8; nf++) {
            Pw[g*68     + nf*8 + 2*t    ] = Sf[nf][0];
            Pw[g*68     + nf*8 + 2*t + 1] = Sf[nf][1];
            Pw[(g+8)*68 + nf*8 + 2*t    ] = Sf[nf][2];
            Pw[(g+8)*68 + nf*8 + 2*t + 1] = Sf[nf][3];
        }
        __syncwarp();

        #pragma unroll
        for (int kc = 0; kc < 4; kc++) {
            const int k = kc*16 + 2*t;
            uint32_t ap[4];
            ap[0] = pack_h2(Pw[g*68     + k],     Pw[g*68     + k + 1]);
            ap[1] = pack_h2(Pw[(g+8)*68 + k],     Pw[(g+8)*68 + k + 1]);
            ap[2] = pack_h2(Pw[g*68     + k + 8], Pw[g*68     + k + 9]);
            ap[3] = pack_h2(Pw[(g+8)*68 + k + 8], Pw[(g+8)*68 + k + 9]);
            #pragma unroll
            for (int nf = 0; nf < 8; nf++) {
                const uint2 v = *reinterpret_cast<const uint2*>(
                    Vs + (nf*4 + kc) * BBLK + lane*2);
                uint32_t bf[2] = { v.x, v.y };
                mma_f16(Of[nf], ap, bf);
            }
        }
    }

    // ---- finalize: divide by l, write fp16 fragment-major ctx ----
    const float inv0 = 1.0f / l0, inv1 = 1.0f / l1;
    const int R0 = b*SS + qb*64 + w*16 + g;
    const int R1 = R0 + 8;
    #pragma unroll
    for (int nf = 0; nf < 8; nf++) {
        const int C = h*DK + nf*8 + 2*t;
        ctx16[a_idx(R0, C, DDIM)] = pack_h2(Of[nf][0]*inv0, Of[nf][1]*inv0);
        ctx16[a_idx(R1, C, DDIM)] = pack_h2(Of[nf][2]*inv1, Of[nf][3]*inv1);
    }
}

// ---------------------------------------------------------------------------
// Launch
// ---------------------------------------------------------------------------
extern "C" void kernel_launch(void* const* d_in, const int* in_sizes, int n_in,
                              void* d_out, int out_size)
{
    const float* x    = (const float*)d_in[0];
    const float* wq   = (const float*)d_in[1];
    const float* bq   = (const float*)d_in[2];
    const float* wk   = (const float*)d_in[3];
    const float* bk   = (const float*)d_in[4];
    const float* wv   = (const float*)d_in[5];
    const float* bv   = (const float*)d_in[6];
    const float* wo   = (const float*)d_in[7];
    const float* bo   = (const float*)d_in[8];
    const float* w1   = (const float*)d_in[9];
    const float* b1   = (const float*)d_in[10];
    const float* w2   = (const float*)d_in[11];
    const float* b2   = (const float*)d_in[12];
    const float* ln1a = (const float*)d_in[13];
    const float* ln1b = (const float*)d_in[14];
    const float* ln2a = (const float*)d_in[15];
    const float* ln2b = (const float*)d_in[16];
    float* out = (float*)d_out;

    float *q, *k, *v, *h;
    uint32_t *xn16, *ctx16, *hn16, *ff16;
    uint32_t *wq16, *wk16, *wv16, *wo16, *w116, *w216;
    cudaGetSymbolAddress((void**)&q,     g_q);
    cudaGetSymbolAddress((void**)&k,     g_k);
    cudaGetSymbolAddress((void**)&v,     g_v);
    cudaGetSymbolAddress((void**)&h,     g_h);
    cudaGetSymbolAddress((void**)&xn16,  g_xn16);
    cudaGetSymbolAddress((void**)&ctx16, g_ctx16);
    cudaGetSymbolAddress((void**)&hn16,  g_hn16);
    cudaGetSymbolAddress((void**)&ff16,  g_ff16);
    cudaGetSymbolAddress((void**)&wq16,  g_wq16);
    cudaGetSymbolAddress((void**)&wk16,  g_wk16);
    cudaGetSymbolAddress((void**)&wv16,  g_wv16);
    cudaGetSymbolAddress((void**)&wo16,  g_wo16);
    cudaGetSymbolAddress((void**)&w116,  g_w116);
    cudaGetSymbolAddress((void**)&w216,  g_w216);

    cudaFuncSetAttribute(gemm_h,
        cudaFuncAttributeMaxDynamicSharedMemorySize, GEMM_DSMEM);

    // weight conversions (once per launch)
    conv_b<<<DDIM*DDIM/16/256, 256>>>(wq, wq16, DDIM, DDIM);
    conv_b<<<DDIM*DDIM/16/256, 256>>>(wk, wk16, DDIM, DDIM);
    conv_b<<<DDIM*DDIM/16/256, 256>>>(wv, wv16, DDIM, DDIM);
    conv_b<<<DDIM*DDIM/16/256, 256>>>(wo, wo16, DDIM, DDIM);
    conv_b<<<FFD*DDIM/16/256,  256>>>(w1, w116, FFD,  DDIM);
    conv_b<<<DDIM*FFD/16/256,  256>>>(w2, w216, DDIM, FFD);

    const dim3 gproj(DDIM/128, MTOT/128);   // (8, 32)
    const dim3 gffn1(FFD/128,  MTOT/128);   // (32, 32)

    ln_kernel<<<MTOT, 256>>>(x, ln1a, ln1b, xn16);
    gemm_h<<<gproj, 256, GEMM_DSMEM>>>(xn16, wq16, bq, nullptr, q,  nullptr, MTOT, DDIM, DDIM, 0);
    gemm_h<<<gproj, 256, GEMM_DSMEM>>>(xn16, wk16, bk, nullptr, k,  nullptr, MTOT, DDIM, DDIM, 0);
    gemm_h<<<gproj, 256, GEMM_DSMEM>>>(xn16, wv16, bv, nullptr, v,  nullptr, MTOT, DDIM, DDIM, 0);
    attn_tc<<<dim3(SS/64, BB*HH), 128>>>(q, k, v, ctx16);
    gemm_h<<<gproj, 256, GEMM_DSMEM>>>(ctx16, wo16, bo, x, h, nullptr, MTOT, DDIM, DDIM, 0);
    ln_kernel<<<MTOT, 256>>>(h, ln2a, ln2b, hn16);
    gemm_h<<<gffn1, 256, GEMM_DSMEM>>>(hn16, w116, b1, nullptr, nullptr, ff16, MTOT, FFD, DDIM, 1);
    gemm_h<<<gproj, 256, GEMM_DSMEM>>>(ff16, w216, b2, h, out, nullptr, MTOT, DDIM, FFD, 0);
}

// round 15
// speedup vs baseline: 2.7223x; 1.2670x over previous
#include <cuda_runtime.h>
#include <cuda_fp16.h>
#include <math.h>
#include <stdint.h>

// Problem constants
#define BB   2
#define SS   2048
#define DDIM 1024
#define HH   16
#define DK   64
#define FFD  4096
#define MTOT (BB*SS)   // 4096 rows
#define HALF_PER_HEAD (SS*DK/2)   // u32 count per (b,h) fragment plane

// ---------------------------------------------------------------------------
// Scratch buffers
// ---------------------------------------------------------------------------
__device__ float    g_v  [MTOT*DDIM];        // V f32 (input to conv_vt)
__device__ float    g_h  [MTOT*DDIM];
__device__ uint32_t g_q16  [MTOT*DDIM/2];    // Q, A-frag
__device__ uint32_t g_kf16 [MTOT*DDIM/2];    // K, B-frag per (b,h)
__device__ uint32_t g_vf16 [MTOT*DDIM/2];    // V, transposed B-frag per (b,h)
__device__ uint32_t g_xn16 [MTOT*DDIM/2];
__device__ uint32_t g_ctx16[MTOT*DDIM/2];
__device__ uint32_t g_hn16 [MTOT*DDIM/2];
__device__ uint32_t g_ff16 [MTOT*FFD/2];
__device__ uint32_t g_wq16[DDIM*DDIM/2];
__device__ uint32_t g_wk16[DDIM*DDIM/2];
__device__ uint32_t g_wv16[DDIM*DDIM/2];
__device__ uint32_t g_wo16[DDIM*DDIM/2];
__device__ uint32_t g_w116[FFD*DDIM/2];
__device__ uint32_t g_w216[DDIM*FFD/2];

// ---------------------------------------------------------------------------
// fp16 helpers + fragment-major layouts (validated R13/R14)
// ---------------------------------------------------------------------------
__device__ __forceinline__ uint32_t pack_h2(float lo, float hi) {
    uint32_t r;
    asm("cvt.rn.f16x2.f32 %0, %1, %2;" : "=r"(r) : "f"(hi), "f"(lo));
    return r;
}

__device__ __forceinline__ void mma_f16(
    float c[4], const uint32_t a[4], const uint32_t b[2])
{
    asm volatile(
        "mma.sync.aligned.m16n8k16.row.col.f32.f16.f16.f32 "
        "{%0,%1,%2,%3}, {%4,%5,%6,%7}, {%8,%9}, {%0,%1,%2,%3};\n"
        : "+f"(c[0]), "+f"(c[1]), "+f"(c[2]), "+f"(c[3])
        : "r"(a[0]), "r"(a[1]), "r"(a[2]), "r"(a[3]), "r"(b[0]), "r"(b[1]));
}

#define ASLOT(rr, p) ( (((rr)&7)*4 + ((p)&3))*4 + (((rr)>>3)&1) + ((((p)>>2)&1)<<1) )
#define BSLOT(n, p)  ( ((n)*8) + (((p)&3)*2) + (((p)>>2)&1) )

// A layout: [mb][kt][mf(8)*4+kc][128]; B layout: [nb][kt][nf(16)*4+kc][64]
__device__ __forceinline__ int a_idx(int R, int k, int K) {
    const int mb = R >> 7, rl = R & 127, mf = rl >> 4, rr = rl & 15;
    const int kt = k >> 6, kc = (k >> 4) & 3, p = (k & 15) >> 1;
    return ((mb * (K >> 6) + kt) * 32 + mf*4 + kc) * 128 + ASLOT(rr, p);
}
__device__ __forceinline__ int b_idx(int n, int k, int K) {
    const int nb = n >> 7, nl = n & 127, nf = nl >> 3, nn = nl & 7;
    const int kt = k >> 6, kc = (k >> 4) & 3, p = (k & 15) >> 1;
    return ((nb * (K >> 6) + kt) * 64 + nf*4 + kc) * 64 + BSLOT(nn, p);
}
// per-(b,h) K fragment plane: block ((s>>3)*4 + (d>>4)), slot BSLOT(s&7,(d&15)>>1)
__device__ __forceinline__ size_t kf_idx(int R, int C) {
    const int b = R >> 11, s = R & 2047;
    const int h = C >> 6, d = C & 63;
    return (size_t)(b*16 + h) * HALF_PER_HEAD
         + (size_t)(((s >> 3) * 4 + (d >> 4)) * 64 + BSLOT(s & 7, (d & 15) >> 1));
}

// ---------------------------------------------------------------------------
// Weight converter: W[N,K] f32 -> fp16 B-frag-major. Vectorized stores.
// ---------------------------------------------------------------------------
__global__ __launch_bounds__(256) void conv_b(
    const float* __restrict__ W, uint32_t* __restrict__ out, int N, int K)
{
    const int t  = blockIdx.x * 256 + threadIdx.x;
    const int nk = K >> 4;
    if (t >= N * nk) return;
    const int n = t / nk, k0 = (t % nk) << 4;
    float w[16];
    const float4* wp = reinterpret_cast<const float4*>(W + (size_t)n * K + k0);
    *reinterpret_cast<float4*>(w)      = wp[0];
    *reinterpret_cast<float4*>(w + 4)  = wp[1];
    *reinterpret_cast<float4*>(w + 8)  = wp[2];
    *reinterpret_cast<float4*>(w + 12) = wp[3];
    uint32_t* d = out + b_idx(n, k0, K);
    uint4 o0, o1;
    o0.x = pack_h2(w[0],  w[1]);  o0.y = pack_h2(w[8],  w[9]);
    o0.z = pack_h2(w[2],  w[3]);  o0.w = pack_h2(w[10], w[11]);
    o1.x = pack_h2(w[4],  w[5]);  o1.y = pack_h2(w[12], w[13]);
    o1.z = pack_h2(w[6],  w[7]);  o1.w = pack_h2(w[14], w[15]);
    *reinterpret_cast<uint4*>(d)     = o0;
    *reinterpret_cast<uint4*>(d + 4) = o1;
}

// ---------------------------------------------------------------------------
// V transpose converter: f32 [R,C] -> per-(b,h) transposed B-frag (k=kv, n=d)
// ---------------------------------------------------------------------------
__global__ __launch_bounds__(128) void conv_vt(
    const float* __restrict__ V, uint32_t* __restrict__ out)
{
    __shared__ float tile[64*68];
    const int tid = threadIdx.x;
    const int kvt = blockIdx.x, bh = blockIdx.y;
    const int b = bh >> 4, h = bh & 15;
    const size_t base = (size_t)b*SS*DDIM + (size_t)kvt*64*DDIM + (size_t)h*DK;
    #pragma unroll
    for (int u = 0; u < 8; u++) {
        const int f = tid + u*128;
        const int r = f >> 4, c4 = (f & 15) << 2;
        *reinterpret_cast<float4*>(tile + r*68 + c4) =
            *reinterpret_cast<const float4*>(V + base + (size_t)r*DDIM + c4);
    }
    __syncthreads();
    uint32_t* ob = out + (size_t)bh * HALF_PER_HEAD + (size_t)kvt * 2048;
    #pragma unroll
    for (int j = 0; j < 16; j++) {
        const int oidx = tid + j*128;
        const int blk = oidx >> 6, slot = oidx & 63;
        const int nf = blk >> 2, kc = blk & 3;
        const int n = slot >> 3, rem = slot & 7;
        const int p = ((rem & 1) << 2) | (rem >> 1);
        const int d = nf*8 + n, kv = kc*16 + 2*p;
        ob[oidx] = pack_h2(tile[kv*68 + d], tile[(kv+1)*68 + d]);
    }
}

// ---------------------------------------------------------------------------
// LayerNorm (faithful math) -> fp16 A-frag output
// ---------------------------------------------------------------------------
__global__ __launch_bounds__(256) void ln_kernel(
    const float* __restrict__ x, const float* __restrict__ alpha,
    const float* __restrict__ beta, uint32_t* __restrict__ y16)
{
    const int row = blockIdx.x;
    const float4* xr = reinterpret_cast<const float4*>(x + (size_t)row * DDIM);
    float4 vv = xr[threadIdx.x];
    float s  = vv.x + vv.y + vv.z + vv.w;
    float s2 = vv.x*vv.x + vv.y*vv.y + vv.z*vv.z + vv.w*vv.w;

    __shared__ float red0[8], red1[8];
    #pragma unroll
    for (int o = 16; o; o >>= 1) {
        s  += __shfl_xor_sync(0xffffffffu, s,  o);
        s2 += __shfl_xor_sync(0xffffffffu, s2, o);
    }
    const int warp = threadIdx.x >> 5, lane = threadIdx.x & 31;
    if (lane == 0) { red0[warp] = s; red1[warp] = s2; }
    __syncthreads();
    if (threadIdx.x == 0) {
        float t = 0.f, t2 = 0.f;
        #pragma unroll
        for (int i = 0; i < 8; i++) { t += red0[i]; t2 += red1[i]; }
        red0[0] = t; red1[0] = t2;
    }
    __syncthreads();
    s = red0[0]; s2 = red1[0];

    const float mean = s * (1.0f / DDIM);
    const float var  = fmaxf(0.f, (s2 - s * mean) * (1.0f / (DDIM - 1)));  // unbiased
    const float stdv = sqrtf(var);
    const float inv  = 1.0f / sqrtf(stdv + 1e-6f);   // sqrt(std + eps) !
    const float a0 = alpha[0], b0 = beta[0];

    const int kq = threadIdx.x * 4;
    float o0 = a0 * (vv.x - mean) * inv + b0;
    float o1 = a0 * (vv.y - mean) * inv + b0;
    float o2 = a0 * (vv.z - mean) * inv + b0;
    float o3 = a0 * (vv.w - mean) * inv + b0;
    const int a = a_idx(row, kq, DDIM);
    y16[a]     = pack_h2(o0, o1);
    y16[a + 4] = pack_h2(o2, o3);
}

// ---------------------------------------------------------------------------
// fp16 GEMM (NT), frag-major operands + cp.async 2-stage pipeline (R14).
// Output modes: Kf (K-fragment planes) > Ch (A-frag chain) > Cf (f32 +res).
// ---------------------------------------------------------------------------
#define GEMM_DSMEM 65536

__global__ __launch_bounds__(256, 2) void gemm_h(
    const uint32_t* __restrict__ Af, const uint32_t* __restrict__ Bf,
    const float* __restrict__ bias, const float* __restrict__ res,
    float* __restrict__ Cf, uint32_t* __restrict__ Ch, uint32_t* __restrict__ Kf,
    int M, int N, int K, int relu)
{
    extern __shared__ uint32_t sm[];

    const int tid  = threadIdx.x;
    const int lane = tid & 31;
    const int warp = tid >> 5;
    const int wm = warp >> 2;
    const int wn = warp & 3;
    const int g  = lane >> 2;
    const int t  = lane & 3;
    const int mb = blockIdx.y, nb = blockIdx.x;
    const int ktN = K >> 6;

    const uint32_t smb = (uint32_t)__cvta_generic_to_shared(sm);

    float acc[4][4][4];
    #pragma unroll
    for (int i = 0; i < 4; i++)
        #pragma unroll
        for (int j = 0; j < 4; j++)
            #pragma unroll
            for (int p = 0; p < 4; p++) acc[i][j][p] = 0.f;

    auto issue = [&](int kt, int s) {
        const uint32_t* sa = Af + (size_t)(mb * ktN + kt) * 4096;
        const uint32_t* sb = Bf + (size_t)(nb * ktN + kt) * 4096;
        const uint32_t da = smb + s * 32768;
        #pragma unroll
        for (int j = 0; j < 4; j++) {
            const int c = tid + j * 256;
            asm volatile("cp.async.cg.shared.global [%0], [%1], 16;"
                :: "r"(da + c*16), "l"(sa + c*4));
        }
        #pragma unroll
        for (int j = 0; j < 4; j++) {
            const int c = tid + j * 256;
            asm volatile("cp.async.cg.shared.global [%0], [%1], 16;"
                :: "r"(da + 16384 + c*16), "l"(sb + c*4));
        }
        asm volatile("cp.async.commit_group;" ::: "memory");
    };

    issue(0, 0);
    for (int kt = 0; kt < ktN; kt++) {
        const int s = kt & 1;
        if (kt + 1 < ktN) {
            issue(kt + 1, s ^ 1);
            asm volatile("cp.async.wait_group 1;" ::: "memory");
        } else {
            asm volatile("cp.async.wait_group 0;" ::: "memory");
        }
        __syncthreads();

        const uint32_t* As = sm + s * 8192;
        const uint32_t* Bs = As + 4096;
        #pragma unroll
        for (int kc = 0; kc < 4; kc++) {
            uint32_t af[4][4];
            #pragma unroll
            for (int mf = 0; mf < 4; mf++) {
                const uint4 v = *reinterpret_cast<const uint4*>(
                    As + ((wm*4 + mf)*4 + kc) * 128 + lane*4);
                af[mf][0] = v.x; af[mf][1] = v.y; af[mf][2] = v.z; af[mf][3] = v.w;
            }
            uint32_t bf[4][2];
            #pragma unroll
            for (int nf = 0; nf < 4; nf++) {
                const uint2 v = *reinterpret_cast<const uint2*>(
                    Bs + ((wn*4 + nf)*4 + kc) * 64 + lane*2);
                bf[nf][0] = v.x; bf[nf][1] = v.y;
            }
            #pragma unroll
            for (int mf = 0; mf < 4; mf++)
                #pragma unroll
                for (int nf = 0; nf < 4; nf++)
                    mma_f16(acc[mf][nf], af[mf], bf[nf]);
        }
        __syncthreads();
    }

    // ---- epilogue ----
    #pragma unroll
    for (int mf = 0; mf < 4; mf++) {
        const int row = mb*128 + wm*64 + mf*16 + g;
        #pragma unroll
        for (int nf = 0; nf < 4; nf++) {
            const int col = nb*128 + wn*32 + nf*8 + t*2;
            const float2 bi = *reinterpret_cast<const float2*>(bias + col);
            float2 c0, c1;
            c0.x = acc[mf][nf][0] + bi.x; c0.y = acc[mf][nf][1] + bi.y;
            c1.x = acc[mf][nf][2] + bi.x; c1.y = acc[mf][nf][3] + bi.y;
            if (relu) {
                c0.x = fmaxf(c0.x, 0.f); c0.y = fmaxf(c0.y, 0.f);
                c1.x = fmaxf(c1.x, 0.f); c1.y = fmaxf(c1.y, 0.f);
            }
            if (Kf) {           // K-fragment plane output
                Kf[kf_idx(row,     col)] = pack_h2(c0.x, c0.y);
                Kf[kf_idx(row + 8, col)] = pack_h2(c1.x, c1.y);
            } else if (Ch) {    // fp16 A-frag chain output
                Ch[a_idx(row,     col, N)] = pack_h2(c0.x, c0.y);
                Ch[a_idx(row + 8, col, N)] = pack_h2(c1.x, c1.y);
            } else {
                const size_t b0 = (size_t)row * N + col;
                const size_t b1 = (size_t)(row + 8) * N + col;
                if (res) {
                    const float2 r0 = *reinterpret_cast<const float2*>(res + b0);
                    const float2 r1 = *reinterpret_cast<const float2*>(res + b1);
                    c0.x += r0.x; c0.y += r0.y;
                    c1.x += r1.x; c1.y += r1.y;
                }
                *reinterpret_cast<float2*>(Cf + b0) = c0;
                *reinterpret_cast<float2*>(Cf + b1) = c1;
            }
        }
    }
}

// ---------------------------------------------------------------------------
// Flash attention, fully register-resident: zero smem, zero barriers.
// Q/K/V consumed as pre-built fragments; S C-frag reused directly as P A-frag.
// 4 warps x 16 q-rows per 64-row tile.
// ---------------------------------------------------------------------------
__global__ __launch_bounds__(128) void attn_tc(
    const uint32_t* __restrict__ q16, const uint32_t* __restrict__ kf,
    const uint32_t* __restrict__ vf, uint32_t* __restrict__ ctx16)
{
    const int tid  = threadIdx.x;
    const int lane = tid & 31;
    const int w    = tid >> 5;
    const int g    = lane >> 2;
    const int t    = lane & 3;
    const int qb   = blockIdx.x;
    const int bh   = blockIdx.y;
    const int b    = bh >> 4, h = bh & 15;

    const uint32_t* kb = kf + (size_t)bh * HALF_PER_HEAD + lane*2;
    const uint32_t* vb = vf + (size_t)bh * HALF_PER_HEAD + lane*2;
    const int R0 = b*SS + qb*64 + w*16 + g;

    // Q fragments straight from global (once)
    uint32_t aq[4][4];
    #pragma unroll
    for (int kc = 0; kc < 4; kc++) {
        const int C = h*64 + kc*16 + 2*t;
        aq[kc][0] = q16[a_idx(R0,     C,     DDIM)];
        aq[kc][1] = q16[a_idx(R0 + 8, C,     DDIM)];
        aq[kc][2] = q16[a_idx(R0,     C + 8, DDIM)];
        aq[kc][3] = q16[a_idx(R0 + 8, C + 8, DDIM)];
    }

    float Of[8][4];
    float m0 = -INFINITY, m1 = -INFINITY, l0 = 0.f, l1 = 0.f;
    #pragma unroll
    for (int nf = 0; nf < 8; nf++)
        #pragma unroll
        for (int p = 0; p < 4; p++) Of[nf][p] = 0.f;

    for (int kv0 = 0; kv0 < SS; kv0 += 64) {
        // ---- S = Q K^T : K frags streamed from global ----
        float Sf[8][4];
        #pragma unroll
        for (int nf = 0; nf < 8; nf++)
            #pragma unroll
            for (int p = 0; p < 4; p++) Sf[nf][p] = 0.f;

        const uint32_t* kt0 = kb + (size_t)(kv0 >> 3) * 256;
        #pragma unroll
        for (int kc = 0; kc < 4; kc++) {
            #pragma unroll
            for (int nf = 0; nf < 8; nf++) {
                const uint2 v = *reinterpret_cast<const uint2*>(kt0 + nf*256 + kc*64);
                uint32_t bf[2] = { v.x, v.y };
                mma_f16(Sf[nf], aq[kc], bf);
            }
        }

        // ---- online softmax (scale 1/8 folded here) ----
        float mx0 = -INFINITY, mx1 = -INFINITY;
        #pragma unroll
        for (int nf = 0; nf < 8; nf++) {
            Sf[nf][0] *= 0.125f; Sf[nf][1] *= 0.125f;
            Sf[nf][2] *= 0.125f; Sf[nf][3] *= 0.125f;
            mx0 = fmaxf(mx0, fmaxf(Sf[nf][0], Sf[nf][1]));
            mx1 = fmaxf(mx1, fmaxf(Sf[nf][2], Sf[nf][3]));
        }
        #pragma unroll
        for (int o = 1; o <= 2; o <<= 1) {
            mx0 = fmaxf(mx0, __shfl_xor_sync(0xffffffffu, mx0, o));
            mx1 = fmaxf(mx1, __shfl_xor_sync(0xffffffffu, mx1, o));
        }
        const float mn0 = fmaxf(m0, mx0), mn1 = fmaxf(m1, mx1);
        const float c0 = __expf(m0 - mn0), c1 = __expf(m1 - mn1);
        m0 = mn0; m1 = mn1;

        float s0 = 0.f, s1 = 0.f;
        #pragma unroll
        for (int nf = 0; nf < 8; nf++) {
            float p0 = __expf(Sf[nf][0] - mn0);
            float p1 = __expf(Sf[nf][1] - mn0);
            float p2 = __expf(Sf[nf][2] - mn1);
            float p3 = __expf(Sf[nf][3] - mn1);
            Sf[nf][0] = p0; Sf[nf][1] = p1; Sf[nf][2] = p2; Sf[nf][3] = p3;
            s0 += p0 + p1; s1 += p2 + p3;
        }
        #pragma unroll
        for (int o = 1; o <= 2; o <<= 1) {
            s0 += __shfl_xor_sync(0xffffffffu, s0, o);
            s1 += __shfl_xor_sync(0xffffffffu, s1, o);
        }
        l0 = l0 * c0 + s0;
        l1 = l1 * c1 + s1;
        #pragma unroll
        for (int nf = 0; nf < 8; nf++) {
            Of[nf][0] *= c0; Of[nf][1] *= c0;
            Of[nf][2] *= c1; Of[nf][3] *= c1;
        }

        // ---- O += P V : S C-frag IS the P A-frag (no permute needed) ----
        const uint32_t* vt0 = vb + (size_t)(kv0 >> 6) * 2048;
        #pragma unroll
        for (int kc = 0; kc < 4; kc++) {
            uint32_t ap[4];
            ap[0] = pack_h2(Sf[2*kc][0],     Sf[2*kc][1]);
            ap[1] = pack_h2(Sf[2*kc][2],     Sf[2*kc][3]);
            ap[2] = pack_h2(Sf[2*kc + 1][0], Sf[2*kc + 1][1]);
            ap[3] = pack_h2(Sf[2*kc + 1][2], Sf[2*kc + 1][3]);
            #pragma unroll
            for (int nf = 0; nf < 8; nf++) {
                const uint2 v = *reinterpret_cast<const uint2*>(vt0 + nf*256 + kc*64);
                uint32_t bf[2] = { v.x, v.y };
                mma_f16(Of[nf], ap, bf);
            }
        }
    }

    // ---- finalize: divide by l, write fp16 A-frag ctx ----
    const float inv0 = 1.0f / l0, inv1 = 1.0f / l1;
    #pragma unroll
    for (int nf = 0; nf < 8; nf++) {
        const int C = h*DK + nf*8 + 2*t;
        ctx16[a_idx(R0,     C, DDIM)] = pack_h2(Of[nf][0]*inv0, Of[nf][1]*inv0);
        ctx16[a_idx(R0 + 8, C, DDIM)] = pack_h2(Of[nf][2]*inv1, Of[nf][3]*inv1);
    }
}

// ---------------------------------------------------------------------------
// Launch
// ---------------------------------------------------------------------------
extern "C" void kernel_launch(void* const* d_in, const int* in_sizes, int n_in,
                              void* d_out, int out_size)
{
    const float* x    = (const float*)d_in[0];
    const float* wq   = (const float*)d_in[1];
    const float* bq   = (const float*)d_in[2];
    const float* wk   = (const float*)d_in[3];
    const float* bk   = (const float*)d_in[4];
    const float* wv   = (const float*)d_in[5];
    const float* bv   = (const float*)d_in[6];
    const float* wo   = (const float*)d_in[7];
    const float* bo   = (const float*)d_in[8];
    const float* w1   = (const float*)d_in[9];
    const float* b1   = (const float*)d_in[10];
    const float* w2   = (const float*)d_in[11];
    const float* b2   = (const float*)d_in[12];
    const float* ln1a = (const float*)d_in[13];
    const float* ln1b = (const float*)d_in[14];
    const float* ln2a = (const float*)d_in[15];
    const float* ln2b = (const float*)d_in[16];
    float* out = (float*)d_out;

    float *v, *h;
    uint32_t *q16, *kf16, *vf16, *xn16, *ctx16, *hn16, *ff16;
    uint32_t *wq16, *wk16, *wv16, *wo16, *w116, *w216;
    cudaGetSymbolAddress((void**)&v,     g_v);
    cudaGetSymbolAddress((void**)&h,     g_h);
    cudaGetSymbolAddress((void**)&q16,   g_q16);
    cudaGetSymbolAddress((void**)&kf16,  g_kf16);
    cudaGetSymbolAddress((void**)&vf16,  g_vf16);
    cudaGetSymbolAddress((void**)&xn16,  g_xn16);
    cudaGetSymbolAddress((void**)&ctx16, g_ctx16);
    cudaGetSymbolAddress((void**)&hn16,  g_hn16);
    cudaGetSymbolAddress((void**)&ff16,  g_ff16);
    cudaGetSymbolAddress((void**)&wq16,  g_wq16);
    cudaGetSymbolAddress((void**)&wk16,  g_wk16);
    cudaGetSymbolAddress((void**)&wv16,  g_wv16);
    cudaGetSymbolAddress((void**)&wo16,  g_wo16);
    cudaGetSymbolAddress((void**)&w116,  g_w116);
    cudaGetSymbolAddress((void**)&w216,  g_w216);

    cudaFuncSetAttribute(gemm_h,
        cudaFuncAttributeMaxDynamicSharedMemorySize, GEMM_DSMEM);

    conv_b<<<DDIM*DDIM/16/256, 256>>>(wq, wq16, DDIM, DDIM);
    conv_b<<<DDIM*DDIM/16/256, 256>>>(wk, wk16, DDIM, DDIM);
    conv_b<<<DDIM*DDIM/16/256, 256>>>(wv, wv16, DDIM, DDIM);
    conv_b<<<DDIM*DDIM/16/256, 256>>>(wo, wo16, DDIM, DDIM);
    conv_b<<<FFD*DDIM/16/256,  256>>>(w1, w116, FFD,  DDIM);
    conv_b<<<DDIM*FFD/16/256,  256>>>(w2, w216, DDIM, FFD);

    const dim3 gproj(DDIM/128, MTOT/128);   // (8, 32)
    const dim3 gffn1(FFD/128,  MTOT/128);   // (32, 32)

    ln_kernel<<<MTOT, 256>>>(x, ln1a, ln1b, xn16);
    gemm_h<<<gproj, 256, GEMM_DSMEM>>>(xn16, wq16, bq, nullptr, nullptr, q16, nullptr, MTOT, DDIM, DDIM, 0);
    gemm_h<<<gproj, 256, GEMM_DSMEM>>>(xn16, wk16, bk, nullptr, nullptr, nullptr, kf16, MTOT, DDIM, DDIM, 0);
    gemm_h<<<gproj, 256, GEMM_DSMEM>>>(xn16, wv16, bv, nullptr, v, nullptr, nullptr, MTOT, DDIM, DDIM, 0);
    conv_vt<<<dim3(SS/64, BB*HH), 128>>>(v, vf16);
    attn_tc<<<dim3(SS/64, BB*HH), 128>>>(q16, kf16, vf16, ctx16);
    gemm_h<<<gproj, 256, GEMM_DSMEM>>>(ctx16, wo16, bo, x, h, nullptr, nullptr, MTOT, DDIM, DDIM, 0);
    ln_kernel<<<MTOT, 256>>>(h, ln2a, ln2b, hn16);
    gemm_h<<<gffn1, 256, GEMM_DSMEM>>>(hn16, w116, b1, nullptr, nullptr, ff16, nullptr, MTOT, FFD, DDIM, 1);
    gemm_h<<<gproj, 256, GEMM_DSMEM>>>(ff16, w216, b2, h, out, nullptr, nullptr, MTOT, DDIM, FFD, 0);
}

// round 17
// speedup vs baseline: 2.8520x; 1.0477x over previous
#include <cuda_runtime.h>
#include <cuda_fp16.h>
#include <math.h>
#include <stdint.h>

// Problem constants
#define BB   2
#define SS   2048
#define DDIM 1024
#define HH   16
#define DK   64
#define FFD  4096
#define MTOT (BB*SS)   // 4096 rows
#define HALF_PER_HEAD (SS*DK/2)   // u32 count per (b,h) fragment plane

// ---------------------------------------------------------------------------
// Scratch buffers
// ---------------------------------------------------------------------------
__device__ float    g_h  [MTOT*DDIM];
__device__ uint32_t g_q16  [MTOT*DDIM/2];    // Q, A-frag
__device__ uint32_t g_kf16 [MTOT*DDIM/2];    // K, B-frag per (b,h)
__device__ uint32_t g_vf16 [MTOT*DDIM/2];    // V, transposed B-frag per (b,h)
__device__ uint32_t g_xn16 [MTOT*DDIM/2];
__device__ uint32_t g_ctx16[MTOT*DDIM/2];
__device__ uint32_t g_hn16 [MTOT*DDIM/2];
__device__ uint32_t g_ff16 [MTOT*FFD/2];
__device__ uint32_t g_wq16[DDIM*DDIM/2];
__device__ uint32_t g_wk16[DDIM*DDIM/2];
__device__ uint32_t g_wv16[DDIM*DDIM/2];
__device__ uint32_t g_wo16[DDIM*DDIM/2];
__device__ uint32_t g_w116[FFD*DDIM/2];
__device__ uint32_t g_w216[DDIM*FFD/2];

// ---------------------------------------------------------------------------
// fp16 helpers + fragment-major layouts (validated R13-R15)
// ---------------------------------------------------------------------------
__device__ __forceinline__ uint32_t pack_h2(float lo, float hi) {
    uint32_t r;
    asm("cvt.rn.f16x2.f32 %0, %1, %2;" : "=r"(r) : "f"(hi), "f"(lo));
    return r;
}

__device__ __forceinline__ void mma_f16(
    float c[4], const uint32_t a[4], const uint32_t b[2])
{
    asm volatile(
        "mma.sync.aligned.m16n8k16.row.col.f32.f16.f16.f32 "
        "{%0,%1,%2,%3}, {%4,%5,%6,%7}, {%8,%9}, {%0,%1,%2,%3};\n"
        : "+f"(c[0]), "+f"(c[1]), "+f"(c[2]), "+f"(c[3])
        : "r"(a[0]), "r"(a[1]), "r"(a[2]), "r"(a[3]), "r"(b[0]), "r"(b[1]));
}

#define ASLOT(rr, p) ( (((rr)&7)*4 + ((p)&3))*4 + (((rr)>>3)&1) + ((((p)>>2)&1)<<1) )
#define BSLOT(n, p)  ( ((n)*8) + (((p)&3)*2) + (((p)>>2)&1) )

// A layout: [mb][kt][mf(8)*4+kc][128]; B layout: [nb][kt][nf(16)*4+kc][64]
__device__ __forceinline__ int a_idx(int R, int k, int K) {
    const int mb = R >> 7, rl = R & 127, mf = rl >> 4, rr = rl & 15;
    const int kt = k >> 6, kc = (k >> 4) & 3, p = (k & 15) >> 1;
    return ((mb * (K >> 6) + kt) * 32 + mf*4 + kc) * 128 + ASLOT(rr, p);
}
__device__ __forceinline__ int b_idx(int n, int k, int K) {
    const int nb = n >> 7, nl = n & 127, nf = nl >> 3, nn = nl & 7;
    const int kt = k >> 6, kc = (k >> 4) & 3, p = (k & 15) >> 1;
    return ((nb * (K >> 6) + kt) * 64 + nf*4 + kc) * 64 + BSLOT(nn, p);
}
// per-(b,h) K fragment plane (n=s, k=d) — k-dim is d, contiguous within head
__device__ __forceinline__ size_t kf_idx(int R, int C) {
    const int b = R >> 11, s = R & 2047;
    const int h = C >> 6, d = C & 63;
    return (size_t)(b*16 + h) * HALF_PER_HEAD
         + (size_t)(((s >> 3) * 4 + (d >> 4)) * 64 + BSLOT(s & 7, (d & 15) >> 1));
}
// per-(b,h) V transposed fragment plane (n=d, k=s); u32 = (s, s+1) pair at d.
// FIXED (R16 bug): tile-major in s — (s>>6)*2048 per 64-kv tile, WITHIN-tile
// kc = (s>>4)&3. Matches the R15 conv_vt layout the attention kernel reads.
__device__ __forceinline__ size_t vf_idx(int R, int C) {
    const int b = R >> 11, s = R & 2047;
    const int h = C >> 6, d = C & 63;
    return (size_t)(b*16 + h) * HALF_PER_HEAD
         + (size_t)((s >> 6) * 2048
                    + ((d >> 3) * 4 + ((s >> 4) & 3)) * 64
                    + BSLOT(d & 7, (s & 15) >> 1));
}

// ---------------------------------------------------------------------------
// Weight converter: W[N,K] f32 -> fp16 B-frag-major. Vectorized stores.
// ---------------------------------------------------------------------------
__global__ __launch_bounds__(256) void conv_b(
    const float* __restrict__ W, uint32_t* __restrict__ out, int N, int K)
{
    const int t  = blockIdx.x * 256 + threadIdx.x;
    const int nk = K >> 4;
    if (t >= N * nk) return;
    const int n = t / nk, k0 = (t % nk) << 4;
    float w[16];
    const float4* wp = reinterpret_cast<const float4*>(W + (size_t)n * K + k0);
    *reinterpret_cast<float4*>(w)      = wp[0];
    *reinterpret_cast<float4*>(w + 4)  = wp[1];
    *reinterpret_cast<float4*>(w + 8)  = wp[2];
    *reinterpret_cast<float4*>(w + 12) = wp[3];
    uint32_t* d = out + b_idx(n, k0, K);
    uint4 o0, o1;
    o0.x = pack_h2(w[0],  w[1]);  o0.y = pack_h2(w[8],  w[9]);
    o0.z = pack_h2(w[2],  w[3]);  o0.w = pack_h2(w[10], w[11]);
    o1.x = pack_h2(w[4],  w[5]);  o1.y = pack_h2(w[12], w[13]);
    o1.z = pack_h2(w[6],  w[7]);  o1.w = pack_h2(w[14], w[15]);
    *reinterpret_cast<uint4*>(d)     = o0;
    *reinterpret_cast<uint4*>(d + 4) = o1;
}

// ---------------------------------------------------------------------------
// LayerNorm, warp-per-row (no barriers): 8 rows per 256-thread block.
// Faithful math: unbiased std, denom = sqrt(std + eps). Output A-frag fp16.
// ---------------------------------------------------------------------------
__global__ __launch_bounds__(256) void ln_kernel(
    const float* __restrict__ x, const float* __restrict__ alpha,
    const float* __restrict__ beta, uint32_t* __restrict__ y16)
{
    const int w    = threadIdx.x >> 5;
    const int lane = threadIdx.x & 31;
    const int row  = blockIdx.x * 8 + w;

    const float4* xr = reinterpret_cast<const float4*>(x + (size_t)row * DDIM);
    float4 v[8];
    float s = 0.f, s2 = 0.f;
    #pragma unroll
    for (int i = 0; i < 8; i++) {
        v[i] = xr[lane + i*32];
        s  += v[i].x + v[i].y + v[i].z + v[i].w;
        s2 += v[i].x*v[i].x + v[i].y*v[i].y + v[i].z*v[i].z + v[i].w*v[i].w;
    }
    #pragma unroll
    for (int o = 16; o; o >>= 1) {
        s  += __shfl_xor_sync(0xffffffffu, s,  o);
        s2 += __shfl_xor_sync(0xffffffffu, s2, o);
    }

    const float mean = s * (1.0f / DDIM);
    const float var  = fmaxf(0.f, (s2 - s * mean) * (1.0f / (DDIM - 1)));  // unbiased
    const float stdv = sqrtf(var);
    const float inv  = 1.0f / sqrtf(stdv + 1e-6f);   // sqrt(std + eps) !
    const float a0 = alpha[0], b0 = beta[0];

    #pragma unroll
    for (int i = 0; i < 8; i++) {
        const int kq = (lane + i*32) * 4;
        const float o0 = a0 * (v[i].x - mean) * inv + b0;
        const float o1 = a0 * (v[i].y - mean) * inv + b0;
        const float o2 = a0 * (v[i].z - mean) * inv + b0;
        const float o3 = a0 * (v[i].w - mean) * inv + b0;
        const int a = a_idx(row, kq, DDIM);
        y16[a]     = pack_h2(o0, o1);
        y16[a + 4] = pack_h2(o2, o3);
    }
}

// ---------------------------------------------------------------------------
// fp16 GEMM (NT), frag-major operands + cp.async 2-stage pipeline.
// 128 threads, 4 warps 2(m)x2(n), warp tile 64x64 (4mf x 8nf) -> 128 B/MMA.
// CTA tile 128x128, K-tile 64 (identical global layouts to R14/R15).
// Output modes: Kf (K-frag planes) > Vf (transposed V-frag planes, shfl-
// paired rows) > Ch (A-frag chain) > Cf (f32 + residual).
// ---------------------------------------------------------------------------
#define GEMM_DSMEM 65536

__global__ __launch_bounds__(128, 2) void gemm_h(
    const uint32_t* __restrict__ Af, const uint32_t* __restrict__ Bf,
    const float* __restrict__ bias, const float* __restrict__ res,
    float* __restrict__ Cf, uint32_t* __restrict__ Ch,
    uint32_t* __restrict__ Kf, uint32_t* __restrict__ Vf,
    int M, int N, int K, int relu)
{
    extern __shared__ uint32_t sm[];

    const int tid  = threadIdx.x;
    const int lane = tid & 31;
    const int warp = tid >> 5;          // 0..3
    const int wm = warp >> 1;           // 0..1
    const int wn = warp & 1;            // 0..1
    const int g  = lane >> 2;           // 0..7
    const int t  = lane & 3;            // 0..3
    const int mb = blockIdx.y, nb = blockIdx.x;
    const int ktN = K >> 6;

    const uint32_t smb = (uint32_t)__cvta_generic_to_shared(sm);

    float acc[4][8][4];
    #pragma unroll
    for (int i = 0; i < 4; i++)
        #pragma unroll
        for (int j = 0; j < 8; j++)
            #pragma unroll
            for (int p = 0; p < 4; p++) acc[i][j][p] = 0.f;

    // one k-tile = A 4096 u32 + B 4096 u32; 128 threads x 8 x 16B each operand
    auto issue = [&](int kt, int s) {
        const uint32_t* sa = Af + (size_t)(mb * ktN + kt) * 4096;
        const uint32_t* sb = Bf + (size_t)(nb * ktN + kt) * 4096;
        const uint32_t da = smb + s * 32768;
        #pragma unroll
        for (int j = 0; j < 8; j++) {
            const int c = tid + j * 128;
            asm volatile("cp.async.cg.shared.global [%0], [%1], 16;"
                :: "r"(da + c*16), "l"(sa + c*4));
        }
        #pragma unroll
        for (int j = 0; j < 8; j++) {
            const int c = tid + j * 128;
            asm volatile("cp.async.cg.shared.global [%0], [%1], 16;"
                :: "r"(da + 16384 + c*16), "l"(sb + c*4));
        }
        asm volatile("cp.async.commit_group;" ::: "memory");
    };

    issue(0, 0);
    for (int kt = 0; kt < ktN; kt++) {
        const int s = kt & 1;
        if (kt + 1 < ktN) {
            issue(kt + 1, s ^ 1);
            asm volatile("cp.async.wait_group 1;" ::: "memory");
        } else {
            asm volatile("cp.async.wait_group 0;" ::: "memory");
        }
        __syncthreads();

        const uint32_t* As = sm + s * 8192;
        const uint32_t* Bs = As + 4096;
        #pragma unroll
        for (int kc = 0; kc < 4; kc++) {
            uint32_t af[4][4];
            #pragma unroll
            for (int mf = 0; mf < 4; mf++) {
                const uint4 v = *reinterpret_cast<const uint4*>(
                    As + ((wm*4 + mf)*4 + kc) * 128 + lane*4);
                af[mf][0] = v.x; af[mf][1] = v.y; af[mf][2] = v.z; af[mf][3] = v.w;
            }
            uint32_t bf[8][2];
            #pragma unroll
            for (int nf = 0; nf < 8; nf++) {
                const uint2 v = *reinterpret_cast<const uint2*>(
                    Bs + ((wn*8 + nf)*4 + kc) * 64 + lane*2);
                bf[nf][0] = v.x; bf[nf][1] = v.y;
            }
            #pragma unroll
            for (int mf = 0; mf < 4; mf++)
                #pragma unroll
                for (int nf = 0; nf < 8; nf++)
                    mma_f16(acc[mf][nf], af[mf], bf[nf]);
        }
        __syncthreads();
    }

    // ---- epilogue ----
    #pragma unroll
    for (int mf = 0; mf < 4; mf++) {
        const int row = mb*128 + wm*64 + mf*16 + g;
        #pragma unroll
        for (int nf = 0; nf < 8; nf++) {
            const int col = nb*128 + wn*64 + nf*8 + t*2;
            const float2 bi = *reinterpret_cast<const float2*>(bias + col);
            float2 c0, c1;
            c0.x = acc[mf][nf][0] + bi.x; c0.y = acc[mf][nf][1] + bi.y;
            c1.x = acc[mf][nf][2] + bi.x; c1.y = acc[mf][nf][3] + bi.y;
            if (relu) {
                c0.x = fmaxf(c0.x, 0.f); c0.y = fmaxf(c0.y, 0.f);
                c1.x = fmaxf(c1.x, 0.f); c1.y = fmaxf(c1.y, 0.f);
            }
            if (Kf) {
                Kf[kf_idx(row,     col)] = pack_h2(c0.x, c0.y);
                Kf[kf_idx(row + 8, col)] = pack_h2(c1.x, c1.y);
            } else if (Vf) {
                // pair rows (g, g+1): partner lane = lane + 4 (same t)
                const float s0x = __shfl_down_sync(0xffffffffu, c0.x, 4);
                const float s0y = __shfl_down_sync(0xffffffffu, c0.y, 4);
                const float s1x = __shfl_down_sync(0xffffffffu, c1.x, 4);
                const float s1y = __shfl_down_sync(0xffffffffu, c1.y, 4);
                if ((g & 1) == 0) {
                    Vf[vf_idx(row,     col    )] = pack_h2(c0.x, s0x);
                    Vf[vf_idx(row,     col + 1)] = pack_h2(c0.y, s0y);
                    Vf[vf_idx(row + 8, col    )] = pack_h2(c1.x, s1x);
                    Vf[vf_idx(row + 8, col + 1)] = pack_h2(c1.y, s1y);
                }
            } else if (Ch) {
                Ch[a_idx(row,     col, N)] = pack_h2(c0.x, c0.y);
                Ch[a_idx(row + 8, col, N)] = pack_h2(c1.x, c1.y);
            } else {
                const size_t b0 = (size_t)row * N + col;
                const size_t b1 = (size_t)(row + 8) * N + col;
                if (res) {
                    const float2 r0 = *reinterpret_cast<const float2*>(res + b0);
                    const float2 r1 = *reinterpret_cast<const float2*>(res + b1);
                    c0.x += r0.x; c0.y += r0.y;
                    c1.x += r1.x; c1.y += r1.y;
                }
                *reinterpret_cast<float2*>(Cf + b0) = c0;
                *reinterpret_cast<float2*>(Cf + b1) = c1;
            }
        }
    }
}

// ---------------------------------------------------------------------------
// Flash attention, fully register-resident (unchanged from passing R15)
// ---------------------------------------------------------------------------
__global__ __launch_bounds__(128) void attn_tc(
    const uint32_t* __restrict__ q16, const uint32_t* __restrict__ kf,
    const uint32_t* __restrict__ vf, uint32_t* __restrict__ ctx16)
{
    const int tid  = threadIdx.x;
    const int lane = tid & 31;
    const int w    = tid >> 5;
    const int g    = lane >> 2;
    const int t    = lane & 3;
    const int qb   = blockIdx.x;
    const int bh   = blockIdx.y;
    const int b    = bh >> 4, h = bh & 15;

    const uint32_t* kb = kf + (size_t)bh * HALF_PER_HEAD + lane*2;
    const uint32_t* vb = vf + (size_t)bh * HALF_PER_HEAD + lane*2;
    const int R0 = b*SS + qb*64 + w*16 + g;

    uint32_t aq[4][4];
    #pragma unroll
    for (int kc = 0; kc < 4; kc++) {
        const int C = h*64 + kc*16 + 2*t;
        aq[kc][0] = q16[a_idx(R0,     C,     DDIM)];
        aq[kc][1] = q16[a_idx(R0 + 8, C,     DDIM)];
        aq[kc][2] = q16[a_idx(R0,     C + 8, DDIM)];
        aq[kc][3] = q16[a_idx(R0 + 8, C + 8, DDIM)];
    }

    float Of[8][4];
    float m0 = -INFINITY, m1 = -INFINITY, l0 = 0.f, l1 = 0.f;
    #pragma unroll
    for (int nf = 0; nf < 8; nf++)
        #pragma unroll
        for (int p = 0; p < 4; p++) Of[nf][p] = 0.f;

    for (int kv0 = 0; kv0 < SS; kv0 += 64) {
        float Sf[8][4];
        #pragma unroll
        for (int nf = 0; nf < 8; nf++)
            #pragma unroll
            for (int p = 0; p < 4; p++) Sf[nf][p] = 0.f;

        const uint32_t* kt0 = kb + (size_t)(kv0 >> 3) * 256;
        #pragma unroll
        for (int kc = 0; kc < 4; kc++) {
            #pragma unroll
            for (int nf = 0; nf < 8; nf++) {
                const uint2 v = *reinterpret_cast<const uint2*>(kt0 + nf*256 + kc*64);
                uint32_t bf[2] = { v.x, v.y };
                mma_f16(Sf[nf], aq[kc], bf);
            }
        }

        float mx0 = -INFINITY, mx1 = -INFINITY;
        #pragma unroll
        for (int nf = 0; nf < 8; nf++) {
            Sf[nf][0] *= 0.125f; Sf[nf][1] *= 0.125f;
            Sf[nf][2] *= 0.125f; Sf[nf][3] *= 0.125f;
            mx0 = fmaxf(mx0, fmaxf(Sf[nf][0], Sf[nf][1]));
            mx1 = fmaxf(mx1, fmaxf(Sf[nf][2], Sf[nf][3]));
        }
        #pragma unroll
        for (int o = 1; o <= 2; o <<= 1) {
            mx0 = fmaxf(mx0, __shfl_xor_sync(0xffffffffu, mx0, o));
            mx1 = fmaxf(mx1, __shfl_xor_sync(0xffffffffu, mx1, o));
        }
        const float mn0 = fmaxf(m0, mx0), mn1 = fmaxf(m1, mx1);
        const float c0 = __expf(m0 - mn0), c1 = __expf(m1 - mn1);
        m0 = mn0; m1 = mn1;

        float s0 = 0.f, s1 = 0.f;
        #pragma unroll
        for (int nf = 0; nf < 8; nf++) {
            float p0 = __expf(Sf[nf][0] - mn0);
            float p1 = __expf(Sf[nf][1] - mn0);
            float p2 = __expf(Sf[nf][2] - mn1);
            float p3 = __expf(Sf[nf][3] - mn1);
            Sf[nf][0] = p0; Sf[nf][1] = p1; Sf[nf][2] = p2; Sf[nf][3] = p3;
            s0 += p0 + p1; s1 += p2 + p3;
        }
        #pragma unroll
        for (int o = 1; o <= 2; o <<= 1) {
            s0 += __shfl_xor_sync(0xffffffffu, s0, o);
            s1 += __shfl_xor_sync(0xffffffffu, s1, o);
        }
        l0 = l0 * c0 + s0;
        l1 = l1 * c1 + s1;
        #pragma unroll
        for (int nf = 0; nf < 8; nf++) {
            Of[nf][0] *= c0; Of[nf][1] *= c0;
            Of[nf][2] *= c1; Of[nf][3] *= c1;
        }

        const uint32_t* vt0 = vb + (size_t)(kv0 >> 6) * 2048;
        #pragma unroll
        for (int kc = 0; kc < 4; kc++) {
            uint32_t ap[4];
            ap[0] = pack_h2(Sf[2*kc][0],     Sf[2*kc][1]);
            ap[1] = pack_h2(Sf[2*kc][2],     Sf[2*kc][3]);
            ap[2] = pack_h2(Sf[2*kc + 1][0], Sf[2*kc + 1][1]);
            ap[3] = pack_h2(Sf[2*kc + 1][2], Sf[2*kc + 1][3]);
            #pragma unroll
            for (int nf = 0; nf < 8; nf++) {
                const uint2 v = *reinterpret_cast<const uint2*>(vt0 + nf*256 + kc*64);
                uint32_t bf[2] = { v.x, v.y };
                mma_f16(Of[nf], ap, bf);
            }
        }
    }

    const float inv0 = 1.0f / l0, inv1 = 1.0f / l1;
    #pragma unroll
    for (int nf = 0; nf < 8; nf++) {
        const int C = h*DK + nf*8 + 2*t;
        ctx16[a_idx(R0,     C, DDIM)] = pack_h2(Of[nf][0]*inv0, Of[nf][1]*inv0);
        ctx16[a_idx(R0 + 8, C, DDIM)] = pack_h2(Of[nf][2]*inv1, Of[nf][3]*inv1);
    }
}

// ---------------------------------------------------------------------------
// Launch
// ---------------------------------------------------------------------------
extern "C" void kernel_launch(void* const* d_in, const int* in_sizes, int n_in,
                              void* d_out, int out_size)
{
    const float* x    = (const float*)d_in[0];
    const float* wq   = (const float*)d_in[1];
    const float* bq   = (const float*)d_in[2];
    const float* wk   = (const float*)d_in[3];
    const float* bk   = (const float*)d_in[4];
    const float* wv   = (const float*)d_in[5];
    const float* bv   = (const float*)d_in[6];
    const float* wo   = (const float*)d_in[7];
    const float* bo   = (const float*)d_in[8];
    const float* w1   = (const float*)d_in[9];
    const float* b1   = (const float*)d_in[10];
    const float* w2   = (const float*)d_in[11];
    const float* b2   = (const float*)d_in[12];
    const float* ln1a = (const float*)d_in[13];
    const float* ln1b = (const float*)d_in[14];
    const float* ln2a = (const float*)d_in[15];
    const float* ln2b = (const float*)d_in[16];
    float* out = (float*)d_out;

    float *h;
    uint32_t *q16, *kf16, *vf16, *xn16, *ctx16, *hn16, *ff16;
    uint32_t *wq16, *wk16, *wv16, *wo16, *w116, *w216;
    cudaGetSymbolAddress((void**)&h,     g_h);
    cudaGetSymbolAddress((void**)&q16,   g_q16);
    cudaGetSymbolAddress((void**)&kf16,  g_kf16);
    cudaGetSymbolAddress((void**)&vf16,  g_vf16);
    cudaGetSymbolAddress((void**)&xn16,  g_xn16);
    cudaGetSymbolAddress((void**)&ctx16, g_ctx16);
    cudaGetSymbolAddress((void**)&hn16,  g_hn16);
    cudaGetSymbolAddress((void**)&ff16,  g_ff16);
    cudaGetSymbolAddress((void**)&wq16,  g_wq16);
    cudaGetSymbolAddress((void**)&wk16,  g_wk16);
    cudaGetSymbolAddress((void**)&wv16,  g_wv16);
    cudaGetSymbolAddress((void**)&wo16,  g_wo16);
    cudaGetSymbolAddress((void**)&w116,  g_w116);
    cudaGetSymbolAddress((void**)&w216,  g_w216);

    cudaFuncSetAttribute(gemm_h,
        cudaFuncAttributeMaxDynamicSharedMemorySize, GEMM_DSMEM);

    conv_b<<<DDIM*DDIM/16/256, 256>>>(wq, wq16, DDIM, DDIM);
    conv_b<<<DDIM*DDIM/16/256, 256>>>(wk, wk16, DDIM, DDIM);
    conv_b<<<DDIM*DDIM/16/256, 256>>>(wv, wv16, DDIM, DDIM);
    conv_b<<<DDIM*DDIM/16/256, 256>>>(wo, wo16, DDIM, DDIM);
    conv_b<<<FFD*DDIM/16/256,  256>>>(w1, w116, FFD,  DDIM);
    conv_b<<<DDIM*FFD/16/256,  256>>>(w2, w216, DDIM, FFD);

    const dim3 gproj(DDIM/128, MTOT/128);   // (8, 32)
    const dim3 gffn1(FFD/128,  MTOT/128);   // (32, 32)

    ln_kernel<<<MTOT/8, 256>>>(x, ln1a, ln1b, xn16);
    gemm_h<<<gproj, 128, GEMM_DSMEM>>>(xn16, wq16, bq, nullptr, nullptr, q16, nullptr, nullptr, MTOT, DDIM, DDIM, 0);
    gemm_h<<<gproj, 128, GEMM_DSMEM>>>(xn16, wk16, bk, nullptr, nullptr, nullptr, kf16, nullptr, MTOT, DDIM, DDIM, 0);
    gemm_h<<<gproj, 128, GEMM_DSMEM>>>(xn16, wv16, bv, nullptr, nullptr, nullptr, nullptr, vf16, MTOT, DDIM, DDIM, 0);
    attn_tc<<<dim3(SS/64, BB*HH), 128>>>(q16, kf16, vf16, ctx16);
    gemm_h<<<gproj, 128, GEMM_DSMEM>>>(ctx16, wo16, bo, x, h, nullptr, nullptr, nullptr, MTOT, DDIM, DDIM, 0);
    ln_kernel<<<MTOT/8, 256>>>(h, ln2a, ln2b, hn16);
    gemm_h<<<gffn1, 128, GEMM_DSMEM>>>(hn16, w116, b1, nullptr, nullptr, ff16, nullptr, nullptr, MTOT, FFD, DDIM, 1);
    gemm_h<<<gproj, 128, GEMM_DSMEM>>>(ff16, w216, b2, h, out, nullptr, nullptr, nullptr, MTOT, DDIM, FFD, 0);
}